// round 2
// baseline (speedup 1.0000x reference)
#include <cuda_runtime.h>
#include <math.h>

#define BB 4
#define NN 2048
#define MM 2048
#define HH 8
#define DHD 64
#define DIMX 512
#define INNERD 512
#define MP 2049
#define MPAD 2112
#define NEG_MAX 3.402823466e38f

// Scratch (device globals; no allocation allowed)
__device__ float g_Q[(size_t)BB*HH*DHD*NN];     // [b,h,d,n]  tanh(q)*scale
__device__ float g_K[(size_t)BB*HH*DHD*MPAD];   // [b,h,d,j]  tanh(k), j=0 null, pads 0
__device__ float g_V[(size_t)BB*HH*MPAD*DHD];   // [b,h,j,d]
__device__ float g_O[(size_t)BB*NN*INNERD];     // [b,n,h*d]
__device__ float g_kbias[BB*MPAD];              // 0 attend / -FLT_MAX masked / -INF pad

// ---------------------------------------------------------------------------
// Generic tiled SGEMM: C[8192 x Ncols] = A[8192 x 512] @ W[512 x Ncols]
// mode 0: Q proj  -> g_Q with tanh*scale epilogue
// mode 1: KV proj -> g_K (tanh) / g_V
// mode 2: out proj (A = g_O) -> d_out + bias
// ---------------------------------------------------------------------------
__global__ __launch_bounds__(256) void gemm_kernel(
    const float* __restrict__ A, const float* __restrict__ W,
    const float* __restrict__ bias, float* __restrict__ out,
    int Ncols, int mode)
{
    __shared__ __align__(16) float As[16][68];
    __shared__ __align__(16) float Bs[16][68];

    const float* Ap = (mode == 2) ? g_O : A;

    int t  = threadIdx.x;
    int tx = t & 15, ty = t >> 4;
    int row0 = blockIdx.y * 64;
    int col0 = blockIdx.x * 64;

    float acc[4][4] = {};

    int lk  = t & 15;   // k within tile for A load
    int lm0 = t >> 4;   // base m for A load

    for (int k0 = 0; k0 < 512; k0 += 16) {
        #pragma unroll
        for (int i = 0; i < 4; i++) {
            int m = lm0 + i * 16;
            As[lk][m] = Ap[(size_t)(row0 + m) * 512 + k0 + lk];
        }
        #pragma unroll
        for (int i = 0; i < 4; i++) {
            int e = t + i * 256;
            int kk = e >> 6, c = e & 63;
            Bs[kk][c] = W[(size_t)(k0 + kk) * Ncols + col0 + c];
        }
        __syncthreads();

        #pragma unroll
        for (int kk = 0; kk < 16; kk++) {
            float4 a4 = *(const float4*)&As[kk][ty * 4];
            float4 b4 = *(const float4*)&Bs[kk][tx * 4];
            float av[4] = {a4.x, a4.y, a4.z, a4.w};
            float bv[4] = {b4.x, b4.y, b4.z, b4.w};
            #pragma unroll
            for (int i = 0; i < 4; i++)
                #pragma unroll
                for (int j = 0; j < 4; j++)
                    acc[i][j] += av[i] * bv[j];
        }
        __syncthreads();
    }

    #pragma unroll
    for (int i = 0; i < 4; i++) {
        #pragma unroll
        for (int j = 0; j < 4; j++) {
            int r = row0 + ty * 4 + i;
            int c = col0 + tx * 4 + j;
            float v = acc[i][j];
            if (mode == 0) {
                int b = r >> 11, n = r & 2047;
                int h = c >> 6,  d = c & 63;
                g_Q[((size_t)(b * HH + h) * DHD + d) * NN + n] = tanhf(v) * 0.125f;
            } else if (mode == 1) {
                int b = r >> 11, m = r & 2047;
                if (c < INNERD) {
                    int h = c >> 6, d = c & 63;
                    g_K[((size_t)(b * HH + h) * DHD + d) * MPAD + (m + 1)] = tanhf(v);
                } else {
                    int c2 = c - INNERD;
                    int h = c2 >> 6, d = c2 & 63;
                    g_V[((size_t)(b * HH + h) * MPAD + (m + 1)) * DHD + d] = v;
                }
            } else {
                out[(size_t)r * 512 + c] = v + bias[c];
            }
        }
    }
}

// ---------------------------------------------------------------------------
// Prep kernels — masks are 32-bit words (bool converted by harness to
// int32 or float32); "nonzero word" == true in either encoding.
// ---------------------------------------------------------------------------
__global__ void prep_bias_kernel(const unsigned int* __restrict__ cmask) {
    int t = blockIdx.x * 256 + threadIdx.x;
    if (t >= BB * MPAD) return;
    int b = t / MPAD, j = t % MPAD;
    float v;
    if (j == 0)        v = 0.f;                                        // null token
    else if (j <= MM)  v = (cmask[b * MM + (j - 1)] != 0u) ? 0.f : -NEG_MAX;
    else               v = -INFINITY;                                  // padding
    g_kbias[t] = v;
}

__global__ void prep_kv_kernel(const float* __restrict__ null_key,
                               const float* __restrict__ null_value) {
    int bh = blockIdx.x;
    float* Kb = g_K + (size_t)bh * DHD * MPAD;
    float* Vb = g_V + (size_t)bh * MPAD * DHD;
    int t = threadIdx.x;
    if (t < DHD) {
        Kb[(size_t)t * MPAD + 0] = tanhf(null_key[t]);
        Vb[t] = null_value[t];
    }
    for (int idx = t; idx < DHD * (MPAD - MP); idx += 256) {
        int d = idx & 63, jr = idx >> 6;
        Kb[(size_t)d * MPAD + MP + jr] = 0.f;
        Vb[(size_t)(MP + jr) * DHD + d] = 0.f;
    }
}

// ---------------------------------------------------------------------------
// Flash-style attention: block = 64 query rows of one (b,h)
// ---------------------------------------------------------------------------
struct __align__(16) AttnSmem {
    float Qt[64][68];   // [d][r]
    float Kt[64][68];   // [d][j]
    float Vs[64][64];   // [j][d]
    float Ss[64][68];   // scores / probs [r][j]
    float mrow[64], lrow[64], arow[64], kb[64];
    int   qm[64];
};

__global__ __launch_bounds__(256) void attn_kernel(const unsigned int* __restrict__ qmask) {
    extern __shared__ char smem_raw[];
    AttnSmem& s = *reinterpret_cast<AttnSmem*>(smem_raw);

    int t  = threadIdx.x;
    int tx = t & 15, ty = t >> 4;
    int n0 = blockIdx.x * 64;
    int h  = blockIdx.y, b = blockIdx.z;
    int bh = b * HH + h;

    const float* Qbase = g_Q + (size_t)bh * DHD * NN;
    const float* Kbase = g_K + (size_t)bh * DHD * MPAD;
    const float* Vbase = g_V + (size_t)bh * MPAD * DHD;

    #pragma unroll
    for (int i = 0; i < 16; i++) {
        int e = t + i * 256;
        int d = e >> 6, r = e & 63;
        s.Qt[d][r] = Qbase[(size_t)d * NN + n0 + r];
    }
    if (t < 64) {
        s.mrow[t] = -NEG_MAX;
        s.lrow[t] = 0.f;
        s.qm[t]   = (qmask[b * NN + n0 + t] != 0u) ? 1 : 0;
    }

    float acc[4][4] = {};

    for (int kt = 0; kt < MPAD / 64; kt++) {
        int j0 = kt * 64;
        #pragma unroll
        for (int i = 0; i < 16; i++) {
            int e = t + i * 256;
            int d = e >> 6, jj = e & 63;
            s.Kt[d][jj] = Kbase[(size_t)d * MPAD + j0 + jj];
        }
        #pragma unroll
        for (int i = 0; i < 16; i++) {
            int e = t + i * 256;
            int jj = e >> 6, d = e & 63;
            s.Vs[jj][d] = Vbase[(size_t)(j0 + jj) * DHD + d];
        }
        if (t < 64) s.kb[t] = g_kbias[b * MPAD + j0 + t];
        __syncthreads();

        // S = (scaled tanh Q)^T tanh K, 4x4 per thread
        float sv[4][4] = {};
        #pragma unroll
        for (int k = 0; k < 64; k++) {
            float4 a4 = *(const float4*)&s.Qt[k][ty * 4];
            float4 b4 = *(const float4*)&s.Kt[k][tx * 4];
            float av[4] = {a4.x, a4.y, a4.z, a4.w};
            float bv[4] = {b4.x, b4.y, b4.z, b4.w};
            #pragma unroll
            for (int i = 0; i < 4; i++)
                #pragma unroll
                for (int j = 0; j < 4; j++)
                    sv[i][j] += av[i] * bv[j];
        }
        // mask + write S
        #pragma unroll
        for (int i = 0; i < 4; i++) {
            int qmr = s.qm[ty * 4 + i];
            float4 o;
            float* po = (float*)&o;
            #pragma unroll
            for (int j = 0; j < 4; j++) {
                float bias = s.kb[tx * 4 + j];
                po[j] = (bias == 0.f) ? (qmr ? sv[i][j] : -NEG_MAX) : bias;
            }
            *(float4*)&s.Ss[ty * 4 + i][tx * 4] = o;
        }
        __syncthreads();

        // online softmax: warp w handles rows w*8 .. w*8+7
        {
            int w = t >> 5, lane = t & 31;
            #pragma unroll
            for (int rr = 0; rr < 8; rr++) {
                int row = w * 8 + rr;
                float x0 = s.Ss[row][lane];
                float x1 = s.Ss[row][lane + 32];
                float mx = fmaxf(x0, x1);
                #pragma unroll
                for (int off = 16; off > 0; off >>= 1)
                    mx = fmaxf(mx, __shfl_xor_sync(0xffffffffu, mx, off));
                float mo = s.mrow[row];
                float mn = fmaxf(mo, mx);
                float p0 = __expf(x0 - mn);
                float p1 = __expf(x1 - mn);
                float sum = p0 + p1;
                #pragma unroll
                for (int off = 16; off > 0; off >>= 1)
                    sum += __shfl_xor_sync(0xffffffffu, sum, off);
                if (lane == 0) {
                    float al = __expf(mo - mn);
                    s.arow[row] = al;
                    s.lrow[row] = s.lrow[row] * al + sum;
                    s.mrow[row] = mn;
                }
                s.Ss[row][lane]      = p0;
                s.Ss[row][lane + 32] = p1;
            }
        }
        __syncthreads();

        // rescale accumulators and add P @ V
        float al[4];
        #pragma unroll
        for (int i = 0; i < 4; i++) al[i] = s.arow[ty * 4 + i];
        #pragma unroll
        for (int i = 0; i < 4; i++)
            #pragma unroll
            for (int j = 0; j < 4; j++)
                acc[i][j] *= al[i];

        #pragma unroll
        for (int jj = 0; jj < 64; jj++) {
            float4 v4 = *(const float4*)&s.Vs[jj][tx * 4];
            float vv[4] = {v4.x, v4.y, v4.z, v4.w};
            float p0 = s.Ss[ty * 4 + 0][jj];
            float p1 = s.Ss[ty * 4 + 1][jj];
            float p2 = s.Ss[ty * 4 + 2][jj];
            float p3 = s.Ss[ty * 4 + 3][jj];
            #pragma unroll
            for (int j = 0; j < 4; j++) {
                acc[0][j] += p0 * vv[j];
                acc[1][j] += p1 * vv[j];
                acc[2][j] += p2 * vv[j];
                acc[3][j] += p3 * vv[j];
            }
        }
        __syncthreads();
    }

    float linv[4];
    #pragma unroll
    for (int i = 0; i < 4; i++) linv[i] = 1.f / s.lrow[ty * 4 + i];

    #pragma unroll
    for (int i = 0; i < 4; i++) {
        int n = n0 + ty * 4 + i;
        #pragma unroll
        for (int j = 0; j < 4; j++) {
            int d = tx * 4 + j;
            g_O[((size_t)b * NN + n) * INNERD + h * DHD + d] = acc[i][j] * linv[i];
        }
    }
}

// ---------------------------------------------------------------------------
extern "C" void kernel_launch(void* const* d_in, const int* in_sizes, int n_in,
                              void* d_out, int out_size) {
    const float* x            = (const float*)d_in[0];
    const float* ctx          = (const float*)d_in[1];
    const unsigned int* mask  = (const unsigned int*)d_in[2];
    const unsigned int* cmask = (const unsigned int*)d_in[3];
    const float* Wq  = (const float*)d_in[4];
    const float* Wkv = (const float*)d_in[5];
    const float* Wo  = (const float*)d_in[6];
    const float* bo  = (const float*)d_in[7];
    const float* nk  = (const float*)d_in[8];
    const float* nv  = (const float*)d_in[9];
    float* out = (float*)d_out;

    cudaFuncSetAttribute(attn_kernel, cudaFuncAttributeMaxDynamicSharedMemorySize,
                         (int)sizeof(AttnSmem));

    prep_bias_kernel<<<(BB * MPAD + 255) / 256, 256>>>(cmask);
    prep_kv_kernel<<<BB * HH, 256>>>(nk, nv);

    dim3 g0(INNERD / 64, (BB * NN) / 64);          // (8, 128)
    gemm_kernel<<<g0, 256>>>(x, Wq, nullptr, nullptr, INNERD, 0);

    dim3 g1((2 * INNERD) / 64, (BB * MM) / 64);    // (16, 128)
    gemm_kernel<<<g1, 256>>>(ctx, Wkv, nullptr, nullptr, 2 * INNERD, 1);

    dim3 ga(NN / 64, HH, BB);                      // (32, 8, 4)
    attn_kernel<<<ga, 256, sizeof(AttnSmem)>>>(mask);

    dim3 g2(512 / 64, (BB * NN) / 64);             // (8, 128)
    gemm_kernel<<<g2, 256>>>(nullptr, Wo, bo, out, 512, 2);
}

// round 3
// speedup vs baseline: 1.0166x; 1.0166x over previous
#include <cuda_runtime.h>
#include <math.h>
#include <stdint.h>

#define BB 4
#define NN 2048
#define MM 2048
#define HH 8
#define DHD 64
#define INNERD 512
#define MP 2049
#define MPAD 2176          // 17 * 128
#define KT 128
#define QT 128
#define NTILES (MPAD / KT) // 17
#define NEG_MAX 3.402823466e38f

// Scratch (device globals; no allocation allowed)
__device__ float g_Q[(size_t)BB*HH*DHD*NN];     // [b,h,d,n]  tanh(q)*scale
__device__ float g_K[(size_t)BB*HH*DHD*MPAD];   // [b,h,d,j]  tanh(k), j=0 null
__device__ float g_V[(size_t)BB*HH*MPAD*DHD];   // [b,h,j,d]
__device__ float g_O[(size_t)BB*NN*INNERD];     // [b,n,h*d]
__device__ float g_kbias[BB*MPAD];              // 0 attend / -FLT_MAX masked / -INF pad

__device__ __forceinline__ void cpa16(void* dst, const void* src) {
    uint32_t d = (uint32_t)__cvta_generic_to_shared(dst);
    asm volatile("cp.async.cg.shared.global [%0], [%1], 16;\n" :: "r"(d), "l"(src));
}
#define CP_COMMIT() asm volatile("cp.async.commit_group;\n" ::: "memory")
#define CP_WAIT(n)  asm volatile("cp.async.wait_group %0;\n" :: "n"(n) : "memory")

// ---------------------------------------------------------------------------
// SGEMM: C[8192 x Ncols] = A[8192 x 512] @ W[512 x Ncols]
// 128x128 tile, 256 thr, 8x8 micro, Kt=16, double buffered.
// mode 0: Q proj -> g_Q (tanh*scale); 1: KV -> g_K(tanh)/g_V; 2: O proj -> out
// ---------------------------------------------------------------------------
__global__ __launch_bounds__(256) void gemm_kernel(
    const float* __restrict__ A, const float* __restrict__ W,
    const float* __restrict__ bias, float* __restrict__ out,
    int Ncols, int mode)
{
    __shared__ __align__(16) float As[2][16][128];
    __shared__ __align__(16) float Bs[2][16][128];

    const float* Ap = (mode == 2) ? g_O : A;
    int t  = threadIdx.x;
    int tx = t & 15, ty = t >> 4;
    int row0 = blockIdx.y * 128, col0 = blockIdx.x * 128;

    int arow = t >> 1, aq = (t & 1) * 8;
    int bk = t >> 4, bc = (t & 15) * 8;

    const float* aptr = Ap + (size_t)(row0 + arow) * 512 + aq;
    const float* bptr = W + (size_t)bk * Ncols + col0 + bc;

    float4 a0 = *(const float4*)(aptr);
    float4 a1 = *(const float4*)(aptr + 4);
    float4 b0 = *(const float4*)(bptr);
    float4 b1 = *(const float4*)(bptr + 4);

    float acc[8][8] = {};
    int p = 0;
    {
        float av[8] = {a0.x,a0.y,a0.z,a0.w,a1.x,a1.y,a1.z,a1.w};
        #pragma unroll
        for (int c = 0; c < 8; c++) As[0][aq + c][arow] = av[c];
        *(float4*)&Bs[0][bk][bc]     = b0;
        *(float4*)&Bs[0][bk][bc + 4] = b1;
    }
    __syncthreads();

    for (int kt = 0; kt < 32; kt++) {
        if (kt < 31) {
            const float* ap = aptr + (kt + 1) * 16;
            const float* bp = bptr + (size_t)(kt + 1) * 16 * Ncols;
            a0 = *(const float4*)(ap);
            a1 = *(const float4*)(ap + 4);
            b0 = *(const float4*)(bp);
            b1 = *(const float4*)(bp + 4);
        }
        #pragma unroll 8
        for (int kk = 0; kk < 16; kk++) {
            float xv[8], yv[8];
            *(float4*)&xv[0] = *(const float4*)&As[p][kk][ty * 8];
            *(float4*)&xv[4] = *(const float4*)&As[p][kk][ty * 8 + 4];
            *(float4*)&yv[0] = *(const float4*)&Bs[p][kk][tx * 8];
            *(float4*)&yv[4] = *(const float4*)&Bs[p][kk][tx * 8 + 4];
            #pragma unroll
            for (int i = 0; i < 8; i++)
                #pragma unroll
                for (int j = 0; j < 8; j++)
                    acc[i][j] += xv[i] * yv[j];
        }
        if (kt < 31) {
            float av[8] = {a0.x,a0.y,a0.z,a0.w,a1.x,a1.y,a1.z,a1.w};
            #pragma unroll
            for (int c = 0; c < 8; c++) As[1 - p][aq + c][arow] = av[c];
            *(float4*)&Bs[1 - p][bk][bc]     = b0;
            *(float4*)&Bs[1 - p][bk][bc + 4] = b1;
            __syncthreads();
            p ^= 1;
        }
    }

    int bidx  = row0 >> 11;
    int nbase = (row0 + ty * 8) & 2047;

    if (mode == 0) {
        #pragma unroll
        for (int j = 0; j < 8; j++) {
            int c = col0 + tx * 8 + j;
            int hh = c >> 6, d = c & 63;
            float* dst = &g_Q[(((size_t)bidx * HH + hh) * DHD + d) * NN + nbase];
            float4 v0 = make_float4(tanhf(acc[0][j])*0.125f, tanhf(acc[1][j])*0.125f,
                                    tanhf(acc[2][j])*0.125f, tanhf(acc[3][j])*0.125f);
            float4 v1 = make_float4(tanhf(acc[4][j])*0.125f, tanhf(acc[5][j])*0.125f,
                                    tanhf(acc[6][j])*0.125f, tanhf(acc[7][j])*0.125f);
            *(float4*)dst = v0; *(float4*)(dst + 4) = v1;
        }
    } else if (mode == 1) {
        if (col0 < INNERD) {
            #pragma unroll
            for (int j = 0; j < 8; j++) {
                int c = col0 + tx * 8 + j;
                int hh = c >> 6, d = c & 63;
                float* dst = &g_K[(((size_t)bidx * HH + hh) * DHD + d) * MPAD + nbase + 1];
                #pragma unroll
                for (int i = 0; i < 8; i++) dst[i] = tanhf(acc[i][j]);
            }
        } else {
            int c2 = col0 - INNERD + tx * 8;
            int hh = c2 >> 6, d = c2 & 63;
            #pragma unroll
            for (int i = 0; i < 8; i++) {
                float* dst = &g_V[(((size_t)bidx * HH + hh) * MPAD + nbase + 1 + i) * DHD + d];
                *(float4*)dst       = make_float4(acc[i][0], acc[i][1], acc[i][2], acc[i][3]);
                *(float4*)(dst + 4) = make_float4(acc[i][4], acc[i][5], acc[i][6], acc[i][7]);
            }
        }
    } else {
        #pragma unroll
        for (int i = 0; i < 8; i++) {
            float* dst = &out[(size_t)(row0 + ty * 8 + i) * 512 + col0 + tx * 8];
            float4 v0 = make_float4(acc[i][0] + bias[col0 + tx*8 + 0], acc[i][1] + bias[col0 + tx*8 + 1],
                                    acc[i][2] + bias[col0 + tx*8 + 2], acc[i][3] + bias[col0 + tx*8 + 3]);
            float4 v1 = make_float4(acc[i][4] + bias[col0 + tx*8 + 4], acc[i][5] + bias[col0 + tx*8 + 5],
                                    acc[i][6] + bias[col0 + tx*8 + 6], acc[i][7] + bias[col0 + tx*8 + 7]);
            *(float4*)dst = v0; *(float4*)(dst + 4) = v1;
        }
    }
}

// ---------------------------------------------------------------------------
// Prep kernels (masks are 32-bit words; nonzero == true)
// ---------------------------------------------------------------------------
__global__ void prep_bias_kernel(const unsigned int* __restrict__ cmask) {
    int t = blockIdx.x * 256 + threadIdx.x;
    if (t >= BB * MPAD) return;
    int b = t / MPAD, j = t % MPAD;
    float v;
    if (j == 0)        v = 0.f;
    else if (j <= MM)  v = (cmask[b * MM + (j - 1)] != 0u) ? 0.f : -NEG_MAX;
    else               v = -INFINITY;
    g_kbias[t] = v;
}

__global__ void prep_kv_kernel(const float* __restrict__ null_key,
                               const float* __restrict__ null_value) {
    int bh = blockIdx.x;
    float* Kb = g_K + (size_t)bh * DHD * MPAD;
    float* Vb = g_V + (size_t)bh * MPAD * DHD;
    int t = threadIdx.x;
    if (t < DHD) {
        Kb[(size_t)t * MPAD + 0] = tanhf(null_key[t]);
        Vb[t] = null_value[t];
    }
    for (int idx = t; idx < DHD * (MPAD - MP); idx += 256) {
        int d = idx & 63, jr = idx >> 6;
        Kb[(size_t)d * MPAD + MP + jr] = 0.f;
        Vb[(size_t)(MP + jr) * DHD + d] = 0.f;
    }
}

// ---------------------------------------------------------------------------
// Flash attention: 128 queries x (b,h) per block, 128-key tiles, cp.async pipe
// ---------------------------------------------------------------------------
struct __align__(16) AttnSmem {
    float Qt[64][128];      // [d][q]
    float Kt[2][64][128];   // [d][j] double buffered
    float Vs[128][64];      // [j][d] single buffered
    float Ss[128][128];     // scores/probs [q][j]
    float mrow[128], lrow[128], arow[128];
    float kb[128];
    int   qm[128];
};

__device__ __forceinline__ void cp_k_tile(AttnSmem& s, int q, const float* Kb, int j0, int t) {
    #pragma unroll
    for (int i = 0; i < 8; i++) {
        int e = t + i * 256;
        int d = e >> 5, c4 = (e & 31) * 4;
        cpa16(&s.Kt[q][d][c4], Kb + (size_t)d * MPAD + j0 + c4);
    }
}
__device__ __forceinline__ void cp_v_tile(AttnSmem& s, const float* Vb, int j0, int t) {
    #pragma unroll
    for (int i = 0; i < 8; i++) {
        int e = t + i * 256;
        int jj = e >> 4, c4 = (e & 15) * 4;
        cpa16(&s.Vs[jj][c4], Vb + (size_t)(j0 + jj) * DHD + c4);
    }
}

__global__ __launch_bounds__(256, 1) void attn_kernel(const unsigned int* __restrict__ qmask) {
    extern __shared__ char smem_raw[];
    AttnSmem& s = *reinterpret_cast<AttnSmem*>(smem_raw);

    int t  = threadIdx.x;
    int tx = t & 15, ty = t >> 4;
    int n0 = blockIdx.x * QT;
    int h  = blockIdx.y, b = blockIdx.z;
    int bh = b * HH + h;

    const float* Qb = g_Q + (size_t)bh * DHD * NN;
    const float* Kb = g_K + (size_t)bh * DHD * MPAD;
    const float* Vb = g_V + (size_t)bh * MPAD * DHD;

    // Q tile (once)
    #pragma unroll
    for (int i = 0; i < 8; i++) {
        int e = t + i * 256;
        int d = e >> 5, c4 = (e & 31) * 4;
        *(float4*)&s.Qt[d][c4] = *(const float4*)&Qb[(size_t)d * NN + n0 + c4];
    }
    if (t < 128) {
        s.mrow[t] = -NEG_MAX;
        s.lrow[t] = 0.f;
        s.qm[t]   = (qmask[b * NN + n0 + t] != 0u) ? 1 : 0;
    }

    cp_k_tile(s, 0, Kb, 0, t);
    CP_COMMIT();

    float acc[8][4] = {};
    int p = 0;

    for (int kt = 0; kt < NTILES; kt++) {
        int j0 = kt * KT;
        if (t < 128) s.kb[t] = g_kbias[b * MPAD + j0 + t];

        cp_v_tile(s, Vb, j0, t);
        CP_COMMIT();
        if (kt < NTILES - 1) {
            cp_k_tile(s, 1 - p, Kb, j0 + KT, t);
            CP_COMMIT();
            CP_WAIT(2);               // K[kt] done
        } else {
            CP_WAIT(1);               // K[last] done
        }
        __syncthreads();

        // ---- S = Q^T K (8x8 micro) ----
        float sv[8][8] = {};
        #pragma unroll 8
        for (int kk = 0; kk < 64; kk++) {
            float qv[8], kv[8];
            *(float4*)&qv[0] = *(const float4*)&s.Qt[kk][ty * 8];
            *(float4*)&qv[4] = *(const float4*)&s.Qt[kk][ty * 8 + 4];
            *(float4*)&kv[0] = *(const float4*)&s.Kt[p][kk][tx * 8];
            *(float4*)&kv[4] = *(const float4*)&s.Kt[p][kk][tx * 8 + 4];
            #pragma unroll
            for (int i = 0; i < 8; i++)
                #pragma unroll
                for (int j = 0; j < 8; j++)
                    sv[i][j] += qv[i] * kv[j];
        }
        // mask + store S
        #pragma unroll
        for (int i = 0; i < 8; i++) {
            int qmr = s.qm[ty * 8 + i];
            float o[8];
            #pragma unroll
            for (int j = 0; j < 8; j++) {
                float bias = s.kb[tx * 8 + j];
                o[j] = (bias == 0.f) ? (qmr ? sv[i][j] : -NEG_MAX) : bias;
            }
            *(float4*)&s.Ss[ty * 8 + i][tx * 8]     = *(float4*)&o[0];
            *(float4*)&s.Ss[ty * 8 + i][tx * 8 + 4] = *(float4*)&o[4];
        }
        __syncthreads();

        // ---- online softmax: warp w owns rows w*16..w*16+15 ----
        {
            int w = t >> 5, lane = t & 31;
            #pragma unroll 4
            for (int rr = 0; rr < 16; rr++) {
                int row = w * 16 + rr;
                float x0 = s.Ss[row][lane];
                float x1 = s.Ss[row][lane + 32];
                float x2 = s.Ss[row][lane + 64];
                float x3 = s.Ss[row][lane + 96];
                float mx = fmaxf(fmaxf(x0, x1), fmaxf(x2, x3));
                #pragma unroll
                for (int off = 16; off > 0; off >>= 1)
                    mx = fmaxf(mx, __shfl_xor_sync(0xffffffffu, mx, off));
                float mo = s.mrow[row];
                float mn = fmaxf(mo, mx);
                float p0 = __expf(x0 - mn);
                float p1 = __expf(x1 - mn);
                float p2 = __expf(x2 - mn);
                float p3 = __expf(x3 - mn);
                float sum = (p0 + p1) + (p2 + p3);
                #pragma unroll
                for (int off = 16; off > 0; off >>= 1)
                    sum += __shfl_xor_sync(0xffffffffu, sum, off);
                if (lane == 0) {
                    float al = __expf(mo - mn);
                    s.arow[row] = al;
                    s.lrow[row] = s.lrow[row] * al + sum;
                    s.mrow[row] = mn;
                }
                s.Ss[row][lane]      = p0;
                s.Ss[row][lane + 32] = p1;
                s.Ss[row][lane + 64] = p2;
                s.Ss[row][lane + 96] = p3;
            }
        }
        if (kt < NTILES - 1) { CP_WAIT(1); } else { CP_WAIT(0); }   // V[kt] done
        __syncthreads();

        // ---- O += P @ V (8x4 micro) ----
        float al8[8];
        #pragma unroll
        for (int i = 0; i < 8; i++) al8[i] = s.arow[ty * 8 + i];
        #pragma unroll
        for (int i = 0; i < 8; i++)
            #pragma unroll
            for (int j = 0; j < 4; j++)
                acc[i][j] *= al8[i];

        #pragma unroll 4
        for (int jj = 0; jj < 128; jj++) {
            float4 v = *(const float4*)&s.Vs[jj][tx * 4];
            #pragma unroll
            for (int i = 0; i < 8; i++) {
                float pi = s.Ss[ty * 8 + i][jj];
                acc[i][0] += pi * v.x;
                acc[i][1] += pi * v.y;
                acc[i][2] += pi * v.z;
                acc[i][3] += pi * v.w;
            }
        }
        __syncthreads();
        p ^= 1;
    }

    #pragma unroll
    for (int i = 0; i < 8; i++) {
        float linv = 1.f / s.lrow[ty * 8 + i];
        size_t base = ((size_t)b * NN + n0 + ty * 8 + i) * INNERD + h * DHD + tx * 4;
        float4 o = make_float4(acc[i][0] * linv, acc[i][1] * linv,
                               acc[i][2] * linv, acc[i][3] * linv);
        *(float4*)&g_O[base] = o;
    }
}

// ---------------------------------------------------------------------------
extern "C" void kernel_launch(void* const* d_in, const int* in_sizes, int n_in,
                              void* d_out, int out_size) {
    const float* x            = (const float*)d_in[0];
    const float* ctx          = (const float*)d_in[1];
    const unsigned int* mask  = (const unsigned int*)d_in[2];
    const unsigned int* cmask = (const unsigned int*)d_in[3];
    const float* Wq  = (const float*)d_in[4];
    const float* Wkv = (const float*)d_in[5];
    const float* Wo  = (const float*)d_in[6];
    const float* bo  = (const float*)d_in[7];
    const float* nk  = (const float*)d_in[8];
    const float* nv  = (const float*)d_in[9];
    float* out = (float*)d_out;

    static int inited = 0;
    if (!inited) {
        cudaFuncSetAttribute(attn_kernel, cudaFuncAttributeMaxDynamicSharedMemorySize,
                             (int)sizeof(AttnSmem));
        inited = 1;
    }

    prep_bias_kernel<<<(BB * MPAD + 255) / 256, 256>>>(cmask);
    prep_kv_kernel<<<BB * HH, 256>>>(nk, nv);

    dim3 g0(INNERD / 128, (BB * NN) / 128);          // (4, 64)
    gemm_kernel<<<g0, 256>>>(x, Wq, nullptr, nullptr, INNERD, 0);

    dim3 g1((2 * INNERD) / 128, (BB * MM) / 128);    // (8, 64)
    gemm_kernel<<<g1, 256>>>(ctx, Wkv, nullptr, nullptr, 2 * INNERD, 1);

    dim3 ga(NN / QT, HH, BB);                        // (16, 8, 4)
    attn_kernel<<<ga, 256, sizeof(AttnSmem)>>>(mask);

    dim3 g2(512 / 128, (BB * NN) / 128);             // (4, 64)
    gemm_kernel<<<g2, 256>>>(nullptr, Wo, bo, out, 512, 2);
}

// round 4
// speedup vs baseline: 1.6316x; 1.6050x over previous
#include <cuda_runtime.h>
#include <math.h>
#include <stdint.h>

#define BB 4
#define NN 2048
#define MM 2048
#define HH 8
#define DHD 64
#define INNERD 512
#define MP 2049
#define MPAD 2176          // 17 * 128
#define KT 128
#define QT 128
#define NTILES (MPAD / KT) // 17
#define NEG_MAX 3.402823466e38f

// Scratch (device globals; no allocation allowed)
__device__ float g_Q[(size_t)BB*HH*NN*DHD];     // [b,h,n,d]  tf32(tanh(q)*scale)
__device__ float g_K[(size_t)BB*HH*DHD*MPAD];   // [b,h,d,j]  tf32(tanh(k)), j=0 null
__device__ float g_V[(size_t)BB*HH*MPAD*DHD];   // [b,h,j,d]  tf32
__device__ float g_O[(size_t)BB*NN*INNERD];     // [b,n,h*d]  fp32
__device__ float g_kbias[BB*MPAD];              // 0 attend / -FLT_MAX masked / -INF pad

__device__ __forceinline__ float to_tf32(float x) {
    float r; asm("cvt.rna.tf32.f32 %0, %1;" : "=f"(r) : "f"(x)); return r;
}
__device__ __forceinline__ void mma_tf32(float* d, uint32_t a0, uint32_t a1,
                                         uint32_t a2, uint32_t a3,
                                         uint32_t b0, uint32_t b1) {
    asm volatile(
        "mma.sync.aligned.m16n8k8.row.col.f32.tf32.tf32.f32 "
        "{%0,%1,%2,%3}, {%4,%5,%6,%7}, {%8,%9}, {%0,%1,%2,%3};"
        : "+f"(d[0]), "+f"(d[1]), "+f"(d[2]), "+f"(d[3])
        : "r"(a0), "r"(a1), "r"(a2), "r"(a3), "r"(b0), "r"(b1));
}
__device__ __forceinline__ void cpa16(void* dst, const void* src) {
    uint32_t d = (uint32_t)__cvta_generic_to_shared(dst);
    asm volatile("cp.async.cg.shared.global [%0], [%1], 16;\n" :: "r"(d), "l"(src));
}
#define CP_COMMIT() asm volatile("cp.async.commit_group;\n" ::: "memory")
#define CP_WAIT(n)  asm volatile("cp.async.wait_group %0;\n" :: "n"(n) : "memory")

// ---------------------------------------------------------------------------
// SGEMM (SIMT fp32): C[8192 x Ncols] = A[8192 x 512] @ W[512 x Ncols]
// mode 0: Q proj -> g_Q; 1: KV -> g_K/g_V; 2: O proj -> out
// ---------------------------------------------------------------------------
__global__ __launch_bounds__(256) void gemm_kernel(
    const float* __restrict__ A, const float* __restrict__ W,
    const float* __restrict__ bias, float* __restrict__ out,
    int Ncols, int mode)
{
    __shared__ __align__(16) float As[2][16][128];
    __shared__ __align__(16) float Bs[2][16][128];

    const float* Ap = (mode == 2) ? g_O : A;
    int t  = threadIdx.x;
    int tx = t & 15, ty = t >> 4;
    int row0 = blockIdx.y * 128, col0 = blockIdx.x * 128;

    int arow = t >> 1, aq = (t & 1) * 8;
    int bk = t >> 4, bc = (t & 15) * 8;

    const float* aptr = Ap + (size_t)(row0 + arow) * 512 + aq;
    const float* bptr = W + (size_t)bk * Ncols + col0 + bc;

    float4 a0 = *(const float4*)(aptr);
    float4 a1 = *(const float4*)(aptr + 4);
    float4 b0 = *(const float4*)(bptr);
    float4 b1 = *(const float4*)(bptr + 4);

    float acc[8][8] = {};
    int p = 0;
    {
        float av[8] = {a0.x,a0.y,a0.z,a0.w,a1.x,a1.y,a1.z,a1.w};
        #pragma unroll
        for (int c = 0; c < 8; c++) As[0][aq + c][arow] = av[c];
        *(float4*)&Bs[0][bk][bc]     = b0;
        *(float4*)&Bs[0][bk][bc + 4] = b1;
    }
    __syncthreads();

    for (int kt = 0; kt < 32; kt++) {
        if (kt < 31) {
            const float* ap = aptr + (kt + 1) * 16;
            const float* bp = bptr + (size_t)(kt + 1) * 16 * Ncols;
            a0 = *(const float4*)(ap);
            a1 = *(const float4*)(ap + 4);
            b0 = *(const float4*)(bp);
            b1 = *(const float4*)(bp + 4);
        }
        #pragma unroll 8
        for (int kk = 0; kk < 16; kk++) {
            float xv[8], yv[8];
            *(float4*)&xv[0] = *(const float4*)&As[p][kk][ty * 8];
            *(float4*)&xv[4] = *(const float4*)&As[p][kk][ty * 8 + 4];
            *(float4*)&yv[0] = *(const float4*)&Bs[p][kk][tx * 8];
            *(float4*)&yv[4] = *(const float4*)&Bs[p][kk][tx * 8 + 4];
            #pragma unroll
            for (int i = 0; i < 8; i++)
                #pragma unroll
                for (int j = 0; j < 8; j++)
                    acc[i][j] += xv[i] * yv[j];
        }
        if (kt < 31) {
            float av[8] = {a0.x,a0.y,a0.z,a0.w,a1.x,a1.y,a1.z,a1.w};
            #pragma unroll
            for (int c = 0; c < 8; c++) As[1 - p][aq + c][arow] = av[c];
            *(float4*)&Bs[1 - p][bk][bc]     = b0;
            *(float4*)&Bs[1 - p][bk][bc + 4] = b1;
            __syncthreads();
            p ^= 1;
        }
    }

    int bidx  = row0 >> 11;
    int nbase = (row0 + ty * 8) & 2047;

    if (mode == 0) {
        // g_Q[b][h][n][d], tf32(tanh(v)*0.125)
        int c0 = col0 + tx * 8;
        int hh = c0 >> 6, d0 = c0 & 63;
        #pragma unroll
        for (int i = 0; i < 8; i++) {
            float* dst = &g_Q[(((size_t)bidx * HH + hh) * NN + nbase + i) * DHD + d0];
            float4 v0 = make_float4(to_tf32(tanhf(acc[i][0])*0.125f), to_tf32(tanhf(acc[i][1])*0.125f),
                                    to_tf32(tanhf(acc[i][2])*0.125f), to_tf32(tanhf(acc[i][3])*0.125f));
            float4 v1 = make_float4(to_tf32(tanhf(acc[i][4])*0.125f), to_tf32(tanhf(acc[i][5])*0.125f),
                                    to_tf32(tanhf(acc[i][6])*0.125f), to_tf32(tanhf(acc[i][7])*0.125f));
            *(float4*)dst = v0; *(float4*)(dst + 4) = v1;
        }
    } else if (mode == 1) {
        if (col0 < INNERD) {
            #pragma unroll
            for (int j = 0; j < 8; j++) {
                int c = col0 + tx * 8 + j;
                int hh = c >> 6, d = c & 63;
                float* dst = &g_K[(((size_t)bidx * HH + hh) * DHD + d) * MPAD + nbase + 1];
                #pragma unroll
                for (int i = 0; i < 8; i++) dst[i] = to_tf32(tanhf(acc[i][j]));
            }
        } else {
            int c2 = col0 - INNERD + tx * 8;
            int hh = c2 >> 6, d = c2 & 63;
            #pragma unroll
            for (int i = 0; i < 8; i++) {
                float* dst = &g_V[(((size_t)bidx * HH + hh) * MPAD + nbase + 1 + i) * DHD + d];
                *(float4*)dst       = make_float4(to_tf32(acc[i][0]), to_tf32(acc[i][1]),
                                                  to_tf32(acc[i][2]), to_tf32(acc[i][3]));
                *(float4*)(dst + 4) = make_float4(to_tf32(acc[i][4]), to_tf32(acc[i][5]),
                                                  to_tf32(acc[i][6]), to_tf32(acc[i][7]));
            }
        }
    } else {
        #pragma unroll
        for (int i = 0; i < 8; i++) {
            float* dst = &out[(size_t)(row0 + ty * 8 + i) * 512 + col0 + tx * 8];
            float4 v0 = make_float4(acc[i][0] + bias[col0 + tx*8 + 0], acc[i][1] + bias[col0 + tx*8 + 1],
                                    acc[i][2] + bias[col0 + tx*8 + 2], acc[i][3] + bias[col0 + tx*8 + 3]);
            float4 v1 = make_float4(acc[i][4] + bias[col0 + tx*8 + 4], acc[i][5] + bias[col0 + tx*8 + 5],
                                    acc[i][6] + bias[col0 + tx*8 + 6], acc[i][7] + bias[col0 + tx*8 + 7]);
            *(float4*)dst = v0; *(float4*)(dst + 4) = v1;
        }
    }
}

// ---------------------------------------------------------------------------
// Prep kernels (masks are 32-bit words; nonzero == true)
// ---------------------------------------------------------------------------
__global__ void prep_bias_kernel(const unsigned int* __restrict__ cmask) {
    int t = blockIdx.x * 256 + threadIdx.x;
    if (t >= BB * MPAD) return;
    int b = t / MPAD, j = t % MPAD;
    float v;
    if (j == 0)        v = 0.f;
    else if (j <= MM)  v = (cmask[b * MM + (j - 1)] != 0u) ? 0.f : -NEG_MAX;
    else               v = -INFINITY;
    g_kbias[t] = v;
}

__global__ void prep_kv_kernel(const float* __restrict__ null_key,
                               const float* __restrict__ null_value) {
    int bh = blockIdx.x;
    float* Kb = g_K + (size_t)bh * DHD * MPAD;
    float* Vb = g_V + (size_t)bh * MPAD * DHD;
    int t = threadIdx.x;
    if (t < DHD) {
        Kb[(size_t)t * MPAD + 0] = to_tf32(tanhf(null_key[t]));
        Vb[t] = to_tf32(null_value[t]);
    }
    for (int idx = t; idx < DHD * (MPAD - MP); idx += 256) {
        int d = idx & 63, jr = idx >> 6;
        Kb[(size_t)d * MPAD + MP + jr] = 0.f;
        Vb[(size_t)(MP + jr) * DHD + d] = 0.f;
    }
}

// ---------------------------------------------------------------------------
// Flash attention with mma.sync tf32 tensor cores.
// Block: 128 q x (b,h). Warp w owns q-rows [w*16, w*16+16).
// ---------------------------------------------------------------------------
struct __align__(16) AttnSmem {
    float Qs[128][68];      // [q][d]
    float Kt[2][64][132];   // [d][j] double buffered
    float Vs[128][68];      // [j][d]
    float Ss[128][132];     // P (probabilities, tf32-rounded)
    float kb[128];
    int   qm[128];
};

__device__ __forceinline__ void cp_k_tile(AttnSmem& s, int q, const float* Kb, int j0, int t) {
    #pragma unroll
    for (int i = 0; i < 8; i++) {
        int e = t + i * 256;
        int d = e >> 5, c4 = (e & 31) * 4;
        cpa16(&s.Kt[q][d][c4], Kb + (size_t)d * MPAD + j0 + c4);
    }
}
__device__ __forceinline__ void cp_v_tile(AttnSmem& s, const float* Vb, int j0, int t) {
    #pragma unroll
    for (int i = 0; i < 8; i++) {
        int e = t + i * 256;
        int jj = e >> 4, c4 = (e & 15) * 4;
        cpa16(&s.Vs[jj][c4], Vb + (size_t)(j0 + jj) * DHD + c4);
    }
}

__global__ __launch_bounds__(256, 1) void attn_kernel(const unsigned int* __restrict__ qmask) {
    extern __shared__ char smem_raw[];
    AttnSmem& s = *reinterpret_cast<AttnSmem*>(smem_raw);

    int t    = threadIdx.x;
    int lane = t & 31, w = t >> 5;
    int n0 = blockIdx.x * QT;
    int h  = blockIdx.y, b = blockIdx.z;
    int bh = b * HH + h;

    const float* Qb = g_Q + (size_t)bh * NN * DHD;
    const float* Kb = g_K + (size_t)bh * DHD * MPAD;
    const float* Vb = g_V + (size_t)bh * MPAD * DHD;

    // Q tile: [q][d], coalesced
    #pragma unroll
    for (int i = 0; i < 8; i++) {
        int e = t + i * 256;
        int q = e >> 4, d4 = (e & 15) * 4;
        *(float4*)&s.Qs[q][d4] = *(const float4*)&Qb[(size_t)(n0 + q) * DHD + d4];
    }
    if (t < 128) s.qm[t] = (qmask[b * NN + n0 + t] != 0u) ? 1 : 0;

    cp_k_tile(s, 0, Kb, 0, t);
    CP_COMMIT();

    int row_lo = w * 16 + (lane >> 2);
    int cl = lane & 3;
    int cg = lane >> 2;
    float m_lo = -NEG_MAX, m_hi = -NEG_MAX, l_lo = 0.f, l_hi = 0.f;
    float oacc[8][4] = {};
    int p = 0;

    for (int kt = 0; kt < NTILES; kt++) {
        int j0 = kt * KT;
        if (t < 128) s.kb[t] = g_kbias[b * MPAD + j0 + t];

        cp_v_tile(s, Vb, j0, t);
        CP_COMMIT();
        if (kt < NTILES - 1) {
            cp_k_tile(s, 1 - p, Kb, j0 + KT, t);
            CP_COMMIT();
            CP_WAIT(2);               // K[kt] ready
        } else {
            CP_WAIT(1);
        }
        __syncthreads();

        // ---- S = Q K^T via mma (16 n-tiles of 8) ----
        float sacc[16][4] = {};
        #pragma unroll
        for (int ko = 0; ko < 8; ko++) {
            int ac = ko * 8 + cl;
            uint32_t a0 = *(const uint32_t*)&s.Qs[row_lo][ac];
            uint32_t a1 = *(const uint32_t*)&s.Qs[row_lo + 8][ac];
            uint32_t a2 = *(const uint32_t*)&s.Qs[row_lo][ac + 4];
            uint32_t a3 = *(const uint32_t*)&s.Qs[row_lo + 8][ac + 4];
            #pragma unroll
            for (int nt = 0; nt < 16; nt++) {
                uint32_t b0 = *(const uint32_t*)&s.Kt[p][ko * 8 + cl][nt * 8 + cg];
                uint32_t b1 = *(const uint32_t*)&s.Kt[p][ko * 8 + 4 + cl][nt * 8 + cg];
                mma_tf32(sacc[nt], a0, a1, a2, a3, b0, b1);
            }
        }

        // ---- register online softmax ----
        int qml = s.qm[row_lo], qmh = s.qm[row_lo + 8];
        float mx_lo = m_lo, mx_hi = m_hi;
        #pragma unroll
        for (int nt = 0; nt < 16; nt++) {
            float k0 = s.kb[nt * 8 + 2 * cl];
            float k1 = s.kb[nt * 8 + 2 * cl + 1];
            float x0 = (k0 == 0.f) ? (qml ? sacc[nt][0] : -NEG_MAX) : k0;
            float x1 = (k1 == 0.f) ? (qml ? sacc[nt][1] : -NEG_MAX) : k1;
            float x2 = (k0 == 0.f) ? (qmh ? sacc[nt][2] : -NEG_MAX) : k0;
            float x3 = (k1 == 0.f) ? (qmh ? sacc[nt][3] : -NEG_MAX) : k1;
            sacc[nt][0] = x0; sacc[nt][1] = x1; sacc[nt][2] = x2; sacc[nt][3] = x3;
            mx_lo = fmaxf(mx_lo, fmaxf(x0, x1));
            mx_hi = fmaxf(mx_hi, fmaxf(x2, x3));
        }
        mx_lo = fmaxf(mx_lo, __shfl_xor_sync(0xffffffffu, mx_lo, 1));
        mx_lo = fmaxf(mx_lo, __shfl_xor_sync(0xffffffffu, mx_lo, 2));
        mx_hi = fmaxf(mx_hi, __shfl_xor_sync(0xffffffffu, mx_hi, 1));
        mx_hi = fmaxf(mx_hi, __shfl_xor_sync(0xffffffffu, mx_hi, 2));

        float al_lo = __expf(m_lo - mx_lo); m_lo = mx_lo;
        float al_hi = __expf(m_hi - mx_hi); m_hi = mx_hi;

        float sum_lo = 0.f, sum_hi = 0.f;
        #pragma unroll
        for (int nt = 0; nt < 16; nt++) {
            float p0 = to_tf32(__expf(sacc[nt][0] - mx_lo));
            float p1 = to_tf32(__expf(sacc[nt][1] - mx_lo));
            float p2 = to_tf32(__expf(sacc[nt][2] - mx_hi));
            float p3 = to_tf32(__expf(sacc[nt][3] - mx_hi));
            sum_lo += p0 + p1;
            sum_hi += p2 + p3;
            int c = nt * 8 + 2 * cl;
            *(float2*)&s.Ss[row_lo][c]     = make_float2(p0, p1);
            *(float2*)&s.Ss[row_lo + 8][c] = make_float2(p2, p3);
        }
        sum_lo += __shfl_xor_sync(0xffffffffu, sum_lo, 1);
        sum_lo += __shfl_xor_sync(0xffffffffu, sum_lo, 2);
        sum_hi += __shfl_xor_sync(0xffffffffu, sum_hi, 1);
        sum_hi += __shfl_xor_sync(0xffffffffu, sum_hi, 2);
        l_lo = l_lo * al_lo + sum_lo;
        l_hi = l_hi * al_hi + sum_hi;
        __syncwarp();

        if (kt < NTILES - 1) { CP_WAIT(1); } else { CP_WAIT(0); }  // V[kt] ready
        __syncthreads();

        // ---- rescale + O += P V via mma ----
        #pragma unroll
        for (int nt = 0; nt < 8; nt++) {
            oacc[nt][0] *= al_lo; oacc[nt][1] *= al_lo;
            oacc[nt][2] *= al_hi; oacc[nt][3] *= al_hi;
        }
        #pragma unroll
        for (int ko = 0; ko < 16; ko++) {
            int ac = ko * 8 + cl;
            uint32_t a0 = *(const uint32_t*)&s.Ss[row_lo][ac];
            uint32_t a1 = *(const uint32_t*)&s.Ss[row_lo + 8][ac];
            uint32_t a2 = *(const uint32_t*)&s.Ss[row_lo][ac + 4];
            uint32_t a3 = *(const uint32_t*)&s.Ss[row_lo + 8][ac + 4];
            #pragma unroll
            for (int nt = 0; nt < 8; nt++) {
                uint32_t b0 = *(const uint32_t*)&s.Vs[ko * 8 + cl][nt * 8 + cg];
                uint32_t b1 = *(const uint32_t*)&s.Vs[ko * 8 + 4 + cl][nt * 8 + cg];
                mma_tf32(oacc[nt], a0, a1, a2, a3, b0, b1);
            }
        }
        __syncthreads();
        p ^= 1;
    }

    float li_lo = 1.f / l_lo, li_hi = 1.f / l_hi;
    #pragma unroll
    for (int nt = 0; nt < 8; nt++) {
        int c = nt * 8 + 2 * cl;
        size_t base_lo = ((size_t)b * NN + n0 + row_lo) * INNERD + h * DHD + c;
        size_t base_hi = ((size_t)b * NN + n0 + row_lo + 8) * INNERD + h * DHD + c;
        *(float2*)&g_O[base_lo] = make_float2(oacc[nt][0] * li_lo, oacc[nt][1] * li_lo);
        *(float2*)&g_O[base_hi] = make_float2(oacc[nt][2] * li_hi, oacc[nt][3] * li_hi);
    }
}

// ---------------------------------------------------------------------------
extern "C" void kernel_launch(void* const* d_in, const int* in_sizes, int n_in,
                              void* d_out, int out_size) {
    const float* x            = (const float*)d_in[0];
    const float* ctx          = (const float*)d_in[1];
    const unsigned int* mask  = (const unsigned int*)d_in[2];
    const unsigned int* cmask = (const unsigned int*)d_in[3];
    const float* Wq  = (const float*)d_in[4];
    const float* Wkv = (const float*)d_in[5];
    const float* Wo  = (const float*)d_in[6];
    const float* bo  = (const float*)d_in[7];
    const float* nk  = (const float*)d_in[8];
    const float* nv  = (const float*)d_in[9];
    float* out = (float*)d_out;

    static int inited = 0;
    if (!inited) {
        cudaFuncSetAttribute(attn_kernel, cudaFuncAttributeMaxDynamicSharedMemorySize,
                             (int)sizeof(AttnSmem));
        inited = 1;
    }

    prep_bias_kernel<<<(BB * MPAD + 255) / 256, 256>>>(cmask);
    prep_kv_kernel<<<BB * HH, 256>>>(nk, nv);

    dim3 g0(INNERD / 128, (BB * NN) / 128);          // (4, 64)
    gemm_kernel<<<g0, 256>>>(x, Wq, nullptr, nullptr, INNERD, 0);

    dim3 g1((2 * INNERD) / 128, (BB * MM) / 128);    // (8, 64)
    gemm_kernel<<<g1, 256>>>(ctx, Wkv, nullptr, nullptr, 2 * INNERD, 1);

    dim3 ga(NN / QT, HH, BB);                        // (16, 8, 4)
    attn_kernel<<<ga, 256, sizeof(AttnSmem)>>>(mask);

    dim3 g2(512 / 128, (BB * NN) / 128);             // (4, 64)
    gemm_kernel<<<g2, 256>>>(nullptr, Wo, bo, out, 512, 2);
}

// round 5
// speedup vs baseline: 2.1640x; 1.3263x over previous
#include <cuda_runtime.h>
#include <math.h>
#include <stdint.h>

#define BB 4
#define NN 2048
#define MM 2048
#define HH 8
#define DHD 64
#define INNERD 512
#define MP 2049
#define MPAD 2176          // 17 * 128
#define KT 128
#define QT 128
#define NTILES (MPAD / KT) // 17
#define NEG_MAX 3.402823466e38f

// Scratch (device globals; no allocation allowed)
__device__ float g_Q[(size_t)BB*HH*NN*DHD];     // [b,h,n,d]  tf32(tanh(q)*scale)
__device__ float g_K[(size_t)BB*HH*DHD*MPAD];   // [b,h,d,j]  tf32(tanh(k)), j=0 null
__device__ float g_V[(size_t)BB*HH*MPAD*DHD];   // [b,h,j,d]  tf32
__device__ float g_O[(size_t)BB*NN*INNERD];     // [b,n,h*d]  tf32-rounded
__device__ float g_kbias[BB*MPAD];              // 0 attend / -FLT_MAX masked / -INF pad
// tf32-pre-rounded inputs
__device__ float g_xr[(size_t)BB*NN*512];
__device__ float g_cr[(size_t)BB*MM*512];
__device__ float g_wq[512*512];
__device__ float g_wkv[512*1024];
__device__ float g_wo[512*512];

__device__ __forceinline__ float to_tf32(float x) {
    float r; asm("cvt.rna.tf32.f32 %0, %1;" : "=f"(r) : "f"(x)); return r;
}
__device__ __forceinline__ void mma_tf32(float* d, uint32_t a0, uint32_t a1,
                                         uint32_t a2, uint32_t a3,
                                         uint32_t b0, uint32_t b1) {
    asm volatile(
        "mma.sync.aligned.m16n8k8.row.col.f32.tf32.tf32.f32 "
        "{%0,%1,%2,%3}, {%4,%5,%6,%7}, {%8,%9}, {%0,%1,%2,%3};"
        : "+f"(d[0]), "+f"(d[1]), "+f"(d[2]), "+f"(d[3])
        : "r"(a0), "r"(a1), "r"(a2), "r"(a3), "r"(b0), "r"(b1));
}
__device__ __forceinline__ void cpa16(void* dst, const void* src) {
    uint32_t d = (uint32_t)__cvta_generic_to_shared(dst);
    asm volatile("cp.async.cg.shared.global [%0], [%1], 16;\n" :: "r"(d), "l"(src));
}
#define CP_COMMIT() asm volatile("cp.async.commit_group;\n" ::: "memory")
#define CP_WAIT(n)  asm volatile("cp.async.wait_group %0;\n" :: "n"(n) : "memory")

// ---------------------------------------------------------------------------
// tf32 pre-round (RNA) of inputs
// ---------------------------------------------------------------------------
__global__ void round_tf32_kernel(const float* __restrict__ src, float* __restrict__ dst, int n4) {
    int i = blockIdx.x * 256 + threadIdx.x;
    if (i >= n4) return;
    float4 v = ((const float4*)src)[i];
    v.x = to_tf32(v.x); v.y = to_tf32(v.y); v.z = to_tf32(v.z); v.w = to_tf32(v.w);
    ((float4*)dst)[i] = v;
}

// ---------------------------------------------------------------------------
// mma tf32 GEMM: C[8192 x Ncols] = A[8192 x 512] @ W[512 x Ncols]
// Block tile 128x128, 8 warps (2x4), warp tile 64x32, k-chunk 16, dbl-buffered.
// mode 0: Q proj -> g_Q (tanh*scale, tf32); 1: KV -> g_K(tanh,tf32)/g_V(tf32);
// mode 2: O proj -> out (+bias, fp32)
// ---------------------------------------------------------------------------
__global__ __launch_bounds__(256) void gemm_mma(
    const float* __restrict__ A, const float* __restrict__ W,
    const float* __restrict__ bias, float* __restrict__ out,
    int Ncols, int mode)
{
    __shared__ __align__(16) float As[2][128][20];   // [m][k], stride 20: conflict-free frags
    __shared__ __align__(16) float Bs[2][16][136];   // [k][n], stride 136: conflict-free frags

    int t = threadIdx.x;
    int lane = t & 31, w = t >> 5;
    int wm = w >> 2, wn = w & 3;          // warp grid 2 x 4
    int rowq = lane >> 2, cl = lane & 3, cg = lane >> 2;
    int row0 = blockIdx.y * 128, col0 = blockIdx.x * 128;

    // load indices
    int am = t >> 1, akq = (t & 1) * 8;            // A: 2 x cpa16 per thread, 8 floats
    int b_k = t >> 4, b_n4 = (t & 15) * 8;         // B: 2 x cpa16 per thread

    float acc[4][4][4] = {};

    // prologue: stage 0
    {
        const float* ap = A + (size_t)(row0 + am) * 512 + akq;
        cpa16(&As[0][am][akq & 15], ap);
        cpa16(&As[0][am][(akq & 15) + 4], ap + 4);
        const float* bp = W + (size_t)b_k * Ncols + col0 + b_n4;
        cpa16(&Bs[0][b_k][b_n4], bp);
        cpa16(&Bs[0][b_k][b_n4 + 4], bp + 4);
    }
    CP_COMMIT();

    int p = 0;
    for (int kt = 0; kt < 32; kt++) {
        if (kt < 31) {
            int k0 = (kt + 1) * 16;
            const float* ap = A + (size_t)(row0 + am) * 512 + k0 + akq;
            cpa16(&As[1 - p][am][akq & 15], ap);
            cpa16(&As[1 - p][am][(akq & 15) + 4], ap + 4);
            const float* bp = W + (size_t)(k0 + b_k) * Ncols + col0 + b_n4;
            cpa16(&Bs[1 - p][b_k][b_n4], bp);
            cpa16(&Bs[1 - p][b_k][b_n4 + 4], bp + 4);
            CP_COMMIT();
            CP_WAIT(1);
        } else {
            CP_WAIT(0);
        }
        __syncthreads();

        #pragma unroll
        for (int ko = 0; ko < 2; ko++) {
            uint32_t af[4][4];
            #pragma unroll
            for (int mi = 0; mi < 4; mi++) {
                int m = wm * 64 + mi * 16 + rowq;
                af[mi][0] = *(const uint32_t*)&As[p][m][ko * 8 + cl];
                af[mi][1] = *(const uint32_t*)&As[p][m + 8][ko * 8 + cl];
                af[mi][2] = *(const uint32_t*)&As[p][m][ko * 8 + cl + 4];
                af[mi][3] = *(const uint32_t*)&As[p][m + 8][ko * 8 + cl + 4];
            }
            #pragma unroll
            for (int ni = 0; ni < 4; ni++) {
                uint32_t b0 = *(const uint32_t*)&Bs[p][ko * 8 + cl][wn * 32 + ni * 8 + cg];
                uint32_t b1 = *(const uint32_t*)&Bs[p][ko * 8 + 4 + cl][wn * 32 + ni * 8 + cg];
                #pragma unroll
                for (int mi = 0; mi < 4; mi++)
                    mma_tf32(acc[mi][ni], af[mi][0], af[mi][1], af[mi][2], af[mi][3], b0, b1);
            }
        }
        __syncthreads();
        p ^= 1;
    }

    // ---- epilogue ----
    int bidx = row0 >> 11;
    #pragma unroll
    for (int mi = 0; mi < 4; mi++) {
        int r0 = row0 + wm * 64 + mi * 16 + rowq;
        int n0r = r0 & 2047;
        #pragma unroll
        for (int ni = 0; ni < 4; ni++) {
            int c = col0 + wn * 32 + ni * 8 + 2 * cl;
            float v0 = acc[mi][ni][0], v1 = acc[mi][ni][1];
            float v2 = acc[mi][ni][2], v3 = acc[mi][ni][3];
            if (mode == 0) {
                int hh = c >> 6, d = c & 63;
                float* d0 = &g_Q[(((size_t)bidx * HH + hh) * NN + n0r) * DHD + d];
                float* d1 = &g_Q[(((size_t)bidx * HH + hh) * NN + n0r + 8) * DHD + d];
                *(float2*)d0 = make_float2(to_tf32(tanhf(v0) * 0.125f), to_tf32(tanhf(v1) * 0.125f));
                *(float2*)d1 = make_float2(to_tf32(tanhf(v2) * 0.125f), to_tf32(tanhf(v3) * 0.125f));
            } else if (mode == 1) {
                if (c < INNERD) {
                    int hh = c >> 6, d = c & 63;
                    float* kb = &g_K[(((size_t)bidx * HH + hh) * DHD + d) * MPAD + n0r + 1];
                    kb[0]            = to_tf32(tanhf(v0));
                    kb[MPAD]         = to_tf32(tanhf(v1));
                    kb[8]            = to_tf32(tanhf(v2));
                    kb[MPAD + 8]     = to_tf32(tanhf(v3));
                } else {
                    int c2 = c - INNERD;
                    int hh = c2 >> 6, d = c2 & 63;
                    float* d0 = &g_V[(((size_t)bidx * HH + hh) * MPAD + n0r + 1) * DHD + d];
                    float* d1 = &g_V[(((size_t)bidx * HH + hh) * MPAD + n0r + 9) * DHD + d];
                    *(float2*)d0 = make_float2(to_tf32(v0), to_tf32(v1));
                    *(float2*)d1 = make_float2(to_tf32(v2), to_tf32(v3));
                }
            } else {
                float b0v = bias[c], b1v = bias[c + 1];
                *(float2*)&out[(size_t)r0 * 512 + c]       = make_float2(v0 + b0v, v1 + b1v);
                *(float2*)&out[(size_t)(r0 + 8) * 512 + c] = make_float2(v2 + b0v, v3 + b1v);
            }
        }
    }
}

// ---------------------------------------------------------------------------
// Prep kernels (masks are 32-bit words; nonzero == true)
// ---------------------------------------------------------------------------
__global__ void prep_bias_kernel(const unsigned int* __restrict__ cmask) {
    int t = blockIdx.x * 256 + threadIdx.x;
    if (t >= BB * MPAD) return;
    int b = t / MPAD, j = t % MPAD;
    float v;
    if (j == 0)        v = 0.f;
    else if (j <= MM)  v = (cmask[b * MM + (j - 1)] != 0u) ? 0.f : -NEG_MAX;
    else               v = -INFINITY;
    g_kbias[t] = v;
}

__global__ void prep_kv_kernel(const float* __restrict__ null_key,
                               const float* __restrict__ null_value) {
    int bh = blockIdx.x;
    float* Kb = g_K + (size_t)bh * DHD * MPAD;
    float* Vb = g_V + (size_t)bh * MPAD * DHD;
    int t = threadIdx.x;
    if (t < DHD) {
        Kb[(size_t)t * MPAD + 0] = to_tf32(tanhf(null_key[t]));
        Vb[t] = to_tf32(null_value[t]);
    }
    for (int idx = t; idx < DHD * (MPAD - MP); idx += 256) {
        int d = idx & 63, jr = idx >> 6;
        Kb[(size_t)d * MPAD + MP + jr] = 0.f;
        Vb[(size_t)(MP + jr) * DHD + d] = 0.f;
    }
}

// ---------------------------------------------------------------------------
// Flash attention with mma.sync tf32 (unchanged from R4 except tf32 O store)
// ---------------------------------------------------------------------------
struct __align__(16) AttnSmem {
    float Qs[128][68];      // [q][d]
    float Kt[2][64][132];   // [d][j] double buffered
    float Vs[128][68];      // [j][d]
    float Ss[128][132];     // P (probabilities, tf32-rounded)
    float kb[128];
    int   qm[128];
};

__device__ __forceinline__ void cp_k_tile(AttnSmem& s, int q, const float* Kb, int j0, int t) {
    #pragma unroll
    for (int i = 0; i < 8; i++) {
        int e = t + i * 256;
        int d = e >> 5, c4 = (e & 31) * 4;
        cpa16(&s.Kt[q][d][c4], Kb + (size_t)d * MPAD + j0 + c4);
    }
}
__device__ __forceinline__ void cp_v_tile(AttnSmem& s, const float* Vb, int j0, int t) {
    #pragma unroll
    for (int i = 0; i < 8; i++) {
        int e = t + i * 256;
        int jj = e >> 4, c4 = (e & 15) * 4;
        cpa16(&s.Vs[jj][c4], Vb + (size_t)(j0 + jj) * DHD + c4);
    }
}

__global__ __launch_bounds__(256, 1) void attn_kernel(const unsigned int* __restrict__ qmask) {
    extern __shared__ char smem_raw[];
    AttnSmem& s = *reinterpret_cast<AttnSmem*>(smem_raw);

    int t    = threadIdx.x;
    int lane = t & 31, w = t >> 5;
    int n0 = blockIdx.x * QT;
    int h  = blockIdx.y, b = blockIdx.z;
    int bh = b * HH + h;

    const float* Qb = g_Q + (size_t)bh * NN * DHD;
    const float* Kb = g_K + (size_t)bh * DHD * MPAD;
    const float* Vb = g_V + (size_t)bh * MPAD * DHD;

    #pragma unroll
    for (int i = 0; i < 8; i++) {
        int e = t + i * 256;
        int q = e >> 4, d4 = (e & 15) * 4;
        *(float4*)&s.Qs[q][d4] = *(const float4*)&Qb[(size_t)(n0 + q) * DHD + d4];
    }
    if (t < 128) s.qm[t] = (qmask[b * NN + n0 + t] != 0u) ? 1 : 0;

    cp_k_tile(s, 0, Kb, 0, t);
    CP_COMMIT();

    int row_lo = w * 16 + (lane >> 2);
    int cl = lane & 3;
    int cg = lane >> 2;
    float m_lo = -NEG_MAX, m_hi = -NEG_MAX, l_lo = 0.f, l_hi = 0.f;
    float oacc[8][4] = {};
    int p = 0;

    for (int kt = 0; kt < NTILES; kt++) {
        int j0 = kt * KT;
        if (t < 128) s.kb[t] = g_kbias[b * MPAD + j0 + t];

        cp_v_tile(s, Vb, j0, t);
        CP_COMMIT();
        if (kt < NTILES - 1) {
            cp_k_tile(s, 1 - p, Kb, j0 + KT, t);
            CP_COMMIT();
            CP_WAIT(2);
        } else {
            CP_WAIT(1);
        }
        __syncthreads();

        // ---- S = Q K^T ----
        float sacc[16][4] = {};
        #pragma unroll
        for (int ko = 0; ko < 8; ko++) {
            int ac = ko * 8 + cl;
            uint32_t a0 = *(const uint32_t*)&s.Qs[row_lo][ac];
            uint32_t a1 = *(const uint32_t*)&s.Qs[row_lo + 8][ac];
            uint32_t a2 = *(const uint32_t*)&s.Qs[row_lo][ac + 4];
            uint32_t a3 = *(const uint32_t*)&s.Qs[row_lo + 8][ac + 4];
            #pragma unroll
            for (int nt = 0; nt < 16; nt++) {
                uint32_t b0 = *(const uint32_t*)&s.Kt[p][ko * 8 + cl][nt * 8 + cg];
                uint32_t b1 = *(const uint32_t*)&s.Kt[p][ko * 8 + 4 + cl][nt * 8 + cg];
                mma_tf32(sacc[nt], a0, a1, a2, a3, b0, b1);
            }
        }

        // ---- register online softmax ----
        int qml = s.qm[row_lo], qmh = s.qm[row_lo + 8];
        float mx_lo = m_lo, mx_hi = m_hi;
        #pragma unroll
        for (int nt = 0; nt < 16; nt++) {
            float k0 = s.kb[nt * 8 + 2 * cl];
            float k1 = s.kb[nt * 8 + 2 * cl + 1];
            float x0 = (k0 == 0.f) ? (qml ? sacc[nt][0] : -NEG_MAX) : k0;
            float x1 = (k1 == 0.f) ? (qml ? sacc[nt][1] : -NEG_MAX) : k1;
            float x2 = (k0 == 0.f) ? (qmh ? sacc[nt][2] : -NEG_MAX) : k0;
            float x3 = (k1 == 0.f) ? (qmh ? sacc[nt][3] : -NEG_MAX) : k1;
            sacc[nt][0] = x0; sacc[nt][1] = x1; sacc[nt][2] = x2; sacc[nt][3] = x3;
            mx_lo = fmaxf(mx_lo, fmaxf(x0, x1));
            mx_hi = fmaxf(mx_hi, fmaxf(x2, x3));
        }
        mx_lo = fmaxf(mx_lo, __shfl_xor_sync(0xffffffffu, mx_lo, 1));
        mx_lo = fmaxf(mx_lo, __shfl_xor_sync(0xffffffffu, mx_lo, 2));
        mx_hi = fmaxf(mx_hi, __shfl_xor_sync(0xffffffffu, mx_hi, 1));
        mx_hi = fmaxf(mx_hi, __shfl_xor_sync(0xffffffffu, mx_hi, 2));

        float al_lo = __expf(m_lo - mx_lo); m_lo = mx_lo;
        float al_hi = __expf(m_hi - mx_hi); m_hi = mx_hi;

        float sum_lo = 0.f, sum_hi = 0.f;
        #pragma unroll
        for (int nt = 0; nt < 16; nt++) {
            float p0 = to_tf32(__expf(sacc[nt][0] - mx_lo));
            float p1 = to_tf32(__expf(sacc[nt][1] - mx_lo));
            float p2 = to_tf32(__expf(sacc[nt][2] - mx_hi));
            float p3 = to_tf32(__expf(sacc[nt][3] - mx_hi));
            sum_lo += p0 + p1;
            sum_hi += p2 + p3;
            int c = nt * 8 + 2 * cl;
            *(float2*)&s.Ss[row_lo][c]     = make_float2(p0, p1);
            *(float2*)&s.Ss[row_lo + 8][c] = make_float2(p2, p3);
        }
        sum_lo += __shfl_xor_sync(0xffffffffu, sum_lo, 1);
        sum_lo += __shfl_xor_sync(0xffffffffu, sum_lo, 2);
        sum_hi += __shfl_xor_sync(0xffffffffu, sum_hi, 1);
        sum_hi += __shfl_xor_sync(0xffffffffu, sum_hi, 2);
        l_lo = l_lo * al_lo + sum_lo;
        l_hi = l_hi * al_hi + sum_hi;
        __syncwarp();

        if (kt < NTILES - 1) { CP_WAIT(1); } else { CP_WAIT(0); }
        __syncthreads();

        // ---- rescale + O += P V ----
        #pragma unroll
        for (int nt = 0; nt < 8; nt++) {
            oacc[nt][0] *= al_lo; oacc[nt][1] *= al_lo;
            oacc[nt][2] *= al_hi; oacc[nt][3] *= al_hi;
        }
        #pragma unroll
        for (int ko = 0; ko < 16; ko++) {
            int ac = ko * 8 + cl;
            uint32_t a0 = *(const uint32_t*)&s.Ss[row_lo][ac];
            uint32_t a1 = *(const uint32_t*)&s.Ss[row_lo + 8][ac];
            uint32_t a2 = *(const uint32_t*)&s.Ss[row_lo][ac + 4];
            uint32_t a3 = *(const uint32_t*)&s.Ss[row_lo + 8][ac + 4];
            #pragma unroll
            for (int nt = 0; nt < 8; nt++) {
                uint32_t b0 = *(const uint32_t*)&s.Vs[ko * 8 + cl][nt * 8 + cg];
                uint32_t b1 = *(const uint32_t*)&s.Vs[ko * 8 + 4 + cl][nt * 8 + cg];
                mma_tf32(oacc[nt], a0, a1, a2, a3, b0, b1);
            }
        }
        __syncthreads();
        p ^= 1;
    }

    float li_lo = 1.f / l_lo, li_hi = 1.f / l_hi;
    #pragma unroll
    for (int nt = 0; nt < 8; nt++) {
        int c = nt * 8 + 2 * cl;
        size_t base_lo = ((size_t)b * NN + n0 + row_lo) * INNERD + h * DHD + c;
        size_t base_hi = ((size_t)b * NN + n0 + row_lo + 8) * INNERD + h * DHD + c;
        *(float2*)&g_O[base_lo] = make_float2(to_tf32(oacc[nt][0] * li_lo), to_tf32(oacc[nt][1] * li_lo));
        *(float2*)&g_O[base_hi] = make_float2(to_tf32(oacc[nt][2] * li_hi), to_tf32(oacc[nt][3] * li_hi));
    }
}

// ---------------------------------------------------------------------------
extern "C" void kernel_launch(void* const* d_in, const int* in_sizes, int n_in,
                              void* d_out, int out_size) {
    const float* x            = (const float*)d_in[0];
    const float* ctx          = (const float*)d_in[1];
    const unsigned int* mask  = (const unsigned int*)d_in[2];
    const unsigned int* cmask = (const unsigned int*)d_in[3];
    const float* Wq  = (const float*)d_in[4];
    const float* Wkv = (const float*)d_in[5];
    const float* Wo  = (const float*)d_in[6];
    const float* bo  = (const float*)d_in[7];
    const float* nk  = (const float*)d_in[8];
    const float* nv  = (const float*)d_in[9];
    float* out = (float*)d_out;

    static int inited = 0;
    if (!inited) {
        cudaFuncSetAttribute(attn_kernel, cudaFuncAttributeMaxDynamicSharedMemorySize,
                             (int)sizeof(AttnSmem));
        inited = 1;
    }

    float* xr;  cudaGetSymbolAddress((void**)&xr,  g_xr);
    float* cr;  cudaGetSymbolAddress((void**)&cr,  g_cr);
    float* wq;  cudaGetSymbolAddress((void**)&wq,  g_wq);
    float* wkv; cudaGetSymbolAddress((void**)&wkv, g_wkv);
    float* wo;  cudaGetSymbolAddress((void**)&wo,  g_wo);

    // pre-round everything to tf32 (RNA) so mma truncation is exact
    round_tf32_kernel<<<(BB*NN*512/4 + 255)/256, 256>>>(x,   xr,  BB*NN*512/4);
    round_tf32_kernel<<<(BB*MM*512/4 + 255)/256, 256>>>(ctx, cr,  BB*MM*512/4);
    round_tf32_kernel<<<(512*512/4   + 255)/256, 256>>>(Wq,  wq,  512*512/4);
    round_tf32_kernel<<<(512*1024/4  + 255)/256, 256>>>(Wkv, wkv, 512*1024/4);
    round_tf32_kernel<<<(512*512/4   + 255)/256, 256>>>(Wo,  wo,  512*512/4);

    prep_bias_kernel<<<(BB * MPAD + 255) / 256, 256>>>(cmask);
    prep_kv_kernel<<<BB * HH, 256>>>(nk, nv);

    dim3 g0(INNERD / 128, (BB * NN) / 128);          // (4, 64)
    gemm_mma<<<g0, 256>>>(xr, wq, nullptr, nullptr, INNERD, 0);

    dim3 g1((2 * INNERD) / 128, (BB * MM) / 128);    // (8, 64)
    gemm_mma<<<g1, 256>>>(cr, wkv, nullptr, nullptr, 2 * INNERD, 1);

    dim3 ga(NN / QT, HH, BB);                        // (16, 8, 4)
    attn_kernel<<<ga, 256, sizeof(AttnSmem)>>>(mask);

    float* oin; cudaGetSymbolAddress((void**)&oin, g_O);
    dim3 g2(512 / 128, (BB * NN) / 128);             // (4, 64)
    gemm_mma<<<g2, 256>>>(oin, wo, bo, out, 512, 2);
}

// round 6
// speedup vs baseline: 4.4290x; 2.0467x over previous
#include <cuda_runtime.h>
#include <cuda_fp16.h>
#include <math.h>
#include <stdint.h>

#define BB 4
#define NN 2048
#define MM 2048
#define HH 8
#define DHD 64
#define INNERD 512
#define MP 2049
#define MPAD 2176          // 17 * 128
#define KT 128
#define QT 128
#define NTILES (MPAD / KT) // 17
#define NEG_MAX 3.402823466e38f

// Scratch (device globals; no allocation allowed) — all fp16 now
__device__ __half g_Qh[(size_t)BB*HH*NN*DHD];    // [b,h,n,d]  tanh(q)*scale
__device__ __half g_Kh[(size_t)BB*HH*MPAD*DHD];  // [b,h,j,d]  tanh(k), j=0 null
__device__ __half g_Vh[(size_t)BB*HH*MPAD*DHD];  // [b,h,j,d]
__device__ __half g_Oh[(size_t)BB*NN*INNERD];    // [b,n,h*d]
__device__ float  g_kbias[BB*MPAD];
__device__ __half g_xh[(size_t)BB*NN*512];
__device__ __half g_ch[(size_t)BB*MM*512];
__device__ __half g_wqh[512*512];
__device__ __half g_wkvh[512*1024];
__device__ __half g_woh[512*512];

__device__ __forceinline__ uint32_t smem_u32(const void* p) {
    return (uint32_t)__cvta_generic_to_shared(p);
}
__device__ __forceinline__ void ldsm4(uint32_t* r, uint32_t a) {
    asm volatile("ldmatrix.sync.aligned.m8n8.x4.shared.b16 {%0,%1,%2,%3}, [%4];"
        : "=r"(r[0]), "=r"(r[1]), "=r"(r[2]), "=r"(r[3]) : "r"(a));
}
__device__ __forceinline__ void ldsm4t(uint32_t* r, uint32_t a) {
    asm volatile("ldmatrix.sync.aligned.m8n8.x4.trans.shared.b16 {%0,%1,%2,%3}, [%4];"
        : "=r"(r[0]), "=r"(r[1]), "=r"(r[2]), "=r"(r[3]) : "r"(a));
}
__device__ __forceinline__ void mma16(float* d, const uint32_t* a, uint32_t b0, uint32_t b1) {
    asm volatile(
        "mma.sync.aligned.m16n8k16.row.col.f32.f16.f16.f32 "
        "{%0,%1,%2,%3}, {%4,%5,%6,%7}, {%8,%9}, {%0,%1,%2,%3};"
        : "+f"(d[0]), "+f"(d[1]), "+f"(d[2]), "+f"(d[3])
        : "r"(a[0]), "r"(a[1]), "r"(a[2]), "r"(a[3]), "r"(b0), "r"(b1));
}
__device__ __forceinline__ void cpa16(void* dst, const void* src) {
    uint32_t d = smem_u32(dst);
    asm volatile("cp.async.cg.shared.global [%0], [%1], 16;\n" :: "r"(d), "l"(src));
}
#define CP_COMMIT() asm volatile("cp.async.commit_group;\n" ::: "memory")
#define CP_WAIT(n)  asm volatile("cp.async.wait_group %0;\n" :: "n"(n) : "memory")

// ---------------------------------------------------------------------------
// fp32 -> fp16 round (RN)
// ---------------------------------------------------------------------------
__global__ void round_h_kernel(const float* __restrict__ src, __half* __restrict__ dst, int n4) {
    int i = blockIdx.x * 256 + threadIdx.x;
    if (i >= n4) return;
    float4 v = ((const float4*)src)[i];
    __half2* d2 = (__half2*)dst;
    d2[2 * i]     = __floats2half2_rn(v.x, v.y);
    d2[2 * i + 1] = __floats2half2_rn(v.z, v.w);
}

// ---------------------------------------------------------------------------
// fp16 mma GEMM: C[8192 x Ncols] = A[8192 x 512] @ W[512 x Ncols], fp32 accum
// Block 128x128, 8 warps (2x4), warp tile 64x32, k-chunk 32, double-buffered.
// mode 0: Q proj; 1: KV proj; 2: O proj -> d_out (+bias, fp32)
// ---------------------------------------------------------------------------
__global__ __launch_bounds__(256) void gemm_mma_h(
    const __half* __restrict__ A, const __half* __restrict__ W,
    const float* __restrict__ bias, float* __restrict__ out,
    int Ncols, int mode)
{
    __shared__ __align__(16) __half As[2][128][40];   // [m][k] pad 40
    __shared__ __align__(16) __half Bs[2][32][136];   // [k][n] pad 136

    int t = threadIdx.x, lane = t & 31, w = t >> 5;
    int wm = w >> 2, wn = w & 3;
    int g = lane >> 2, cl = lane & 3;
    int row0 = blockIdx.y * 128, col0 = blockIdx.x * 128;

    int ar0 = t >> 2, ac = (t & 3) * 8;      // A: rows ar0, ar0+64
    int br0 = t >> 4, bc = (t & 15) * 8;     // B: rows br0, br0+16

    float acc[4][4][4] = {};

    // prologue
    cpa16(&As[0][ar0][ac],      A + (size_t)(row0 + ar0) * 512 + ac);
    cpa16(&As[0][ar0 + 64][ac], A + (size_t)(row0 + ar0 + 64) * 512 + ac);
    cpa16(&Bs[0][br0][bc],      W + (size_t)br0 * Ncols + col0 + bc);
    cpa16(&Bs[0][br0 + 16][bc], W + (size_t)(br0 + 16) * Ncols + col0 + bc);
    CP_COMMIT();

    int a_lr = lane & 15, a_lc = (lane >> 4) * 8;                  // A-frag lane map
    int b_lr = (lane & 7) + 8 * ((lane >> 3) & 1), b_lc = 8 * (lane >> 4); // B-frag (trans)

    int p = 0;
    for (int kt = 0; kt < 16; kt++) {
        if (kt < 15) {
            int k0 = (kt + 1) * 32;
            cpa16(&As[1 - p][ar0][ac],      A + (size_t)(row0 + ar0) * 512 + k0 + ac);
            cpa16(&As[1 - p][ar0 + 64][ac], A + (size_t)(row0 + ar0 + 64) * 512 + k0 + ac);
            cpa16(&Bs[1 - p][br0][bc],      W + (size_t)(k0 + br0) * Ncols + col0 + bc);
            cpa16(&Bs[1 - p][br0 + 16][bc], W + (size_t)(k0 + br0 + 16) * Ncols + col0 + bc);
            CP_COMMIT(); CP_WAIT(1);
        } else {
            CP_WAIT(0);
        }
        __syncthreads();

        #pragma unroll
        for (int kc = 0; kc < 2; kc++) {
            uint32_t af[4][4];
            #pragma unroll
            for (int mi = 0; mi < 4; mi++)
                ldsm4(af[mi], smem_u32(&As[p][wm * 64 + mi * 16 + a_lr][kc * 16 + a_lc]));
            #pragma unroll
            for (int np = 0; np < 2; np++) {
                uint32_t bf[4];
                ldsm4t(bf, smem_u32(&Bs[p][kc * 16 + b_lr][wn * 32 + np * 16 + b_lc]));
                #pragma unroll
                for (int mi = 0; mi < 4; mi++) {
                    mma16(acc[mi][np * 2],     af[mi], bf[0], bf[1]);
                    mma16(acc[mi][np * 2 + 1], af[mi], bf[2], bf[3]);
                }
            }
        }
        __syncthreads();
        p ^= 1;
    }

    // epilogue
    int bidx = row0 >> 11;
    #pragma unroll
    for (int mi = 0; mi < 4; mi++) {
        int r0 = row0 + wm * 64 + mi * 16 + g;
        int n0r = r0 & 2047;
        #pragma unroll
        for (int ni = 0; ni < 4; ni++) {
            int c = col0 + wn * 32 + ni * 8 + 2 * cl;
            float v0 = acc[mi][ni][0], v1 = acc[mi][ni][1];
            float v2 = acc[mi][ni][2], v3 = acc[mi][ni][3];
            if (mode == 0) {
                int hh = c >> 6, d = c & 63;
                *(__half2*)&g_Qh[(((size_t)bidx * HH + hh) * NN + n0r) * DHD + d] =
                    __floats2half2_rn(tanhf(v0) * 0.125f, tanhf(v1) * 0.125f);
                *(__half2*)&g_Qh[(((size_t)bidx * HH + hh) * NN + n0r + 8) * DHD + d] =
                    __floats2half2_rn(tanhf(v2) * 0.125f, tanhf(v3) * 0.125f);
            } else if (mode == 1) {
                if (c < INNERD) {
                    int hh = c >> 6, d = c & 63;
                    *(__half2*)&g_Kh[(((size_t)bidx * HH + hh) * MPAD + n0r + 1) * DHD + d] =
                        __floats2half2_rn(tanhf(v0), tanhf(v1));
                    *(__half2*)&g_Kh[(((size_t)bidx * HH + hh) * MPAD + n0r + 9) * DHD + d] =
                        __floats2half2_rn(tanhf(v2), tanhf(v3));
                } else {
                    int c2 = c - INNERD;
                    int hh = c2 >> 6, d = c2 & 63;
                    *(__half2*)&g_Vh[(((size_t)bidx * HH + hh) * MPAD + n0r + 1) * DHD + d] =
                        __floats2half2_rn(v0, v1);
                    *(__half2*)&g_Vh[(((size_t)bidx * HH + hh) * MPAD + n0r + 9) * DHD + d] =
                        __floats2half2_rn(v2, v3);
                }
            } else {
                float b0v = bias[c], b1v = bias[c + 1];
                *(float2*)&out[(size_t)r0 * 512 + c]       = make_float2(v0 + b0v, v1 + b1v);
                *(float2*)&out[(size_t)(r0 + 8) * 512 + c] = make_float2(v2 + b0v, v3 + b1v);
            }
        }
    }
}

// ---------------------------------------------------------------------------
// Prep kernels (masks are 32-bit words; nonzero == true)
// ---------------------------------------------------------------------------
__global__ void prep_bias_kernel(const unsigned int* __restrict__ cmask) {
    int t = blockIdx.x * 256 + threadIdx.x;
    if (t >= BB * MPAD) return;
    int b = t / MPAD, j = t % MPAD;
    float v;
    if (j == 0)        v = 0.f;
    else if (j <= MM)  v = (cmask[b * MM + (j - 1)] != 0u) ? 0.f : -NEG_MAX;
    else               v = -INFINITY;
    g_kbias[t] = v;
}

__global__ void prep_kv_kernel(const float* __restrict__ null_key,
                               const float* __restrict__ null_value) {
    int bh = blockIdx.x;
    __half* Kb = g_Kh + (size_t)bh * MPAD * DHD;
    __half* Vb = g_Vh + (size_t)bh * MPAD * DHD;
    int t = threadIdx.x;
    if (t < DHD) {
        Kb[t] = __float2half_rn(tanhf(null_key[t]));
        Vb[t] = __float2half_rn(null_value[t]);
    }
    for (int idx = t; idx < DHD * (MPAD - MP); idx += 256) {
        int d = idx & 63, jr = idx >> 6;
        Kb[(size_t)(MP + jr) * DHD + d] = __float2half_rn(0.f);
        Vb[(size_t)(MP + jr) * DHD + d] = __float2half_rn(0.f);
    }
}

// ---------------------------------------------------------------------------
// Flash attention, fp16 mma m16n8k16 + ldmatrix.
// Block: 128 q x (b,h), 8 warps x 16 q-rows, 128-key tiles.
// ---------------------------------------------------------------------------
struct __align__(16) AttnSmemH {
    __half Qs[128][72];      // [q][d]
    __half Kt[2][128][72];   // [j][d] double buffered
    __half Vs[128][72];      // [j][d]
    __half Ss[128][136];     // P fp16
    float kb[128];
    int   qm[128];
};

__device__ __forceinline__ void cp_k_tile_h(AttnSmemH& s, int buf, const __half* Kb, int j0, int t) {
    #pragma unroll
    for (int i = 0; i < 4; i++) {
        int e = t + i * 256;
        int r = e >> 3, c8 = (e & 7) * 8;
        cpa16(&s.Kt[buf][r][c8], Kb + (size_t)(j0 + r) * DHD + c8);
    }
}
__device__ __forceinline__ void cp_v_tile_h(AttnSmemH& s, const __half* Vb, int j0, int t) {
    #pragma unroll
    for (int i = 0; i < 4; i++) {
        int e = t + i * 256;
        int r = e >> 3, c8 = (e & 7) * 8;
        cpa16(&s.Vs[r][c8], Vb + (size_t)(j0 + r) * DHD + c8);
    }
}

__global__ __launch_bounds__(256) void attn_kernel(const unsigned int* __restrict__ qmask) {
    extern __shared__ char smem_raw[];
    AttnSmemH& s = *reinterpret_cast<AttnSmemH*>(smem_raw);

    int t = threadIdx.x, lane = t & 31, w = t >> 5;
    int n0 = blockIdx.x * QT;
    int h = blockIdx.y, b = blockIdx.z;
    int bh = b * HH + h;

    const __half* Qb = g_Qh + (size_t)bh * NN * DHD;
    const __half* Kb = g_Kh + (size_t)bh * MPAD * DHD;
    const __half* Vb = g_Vh + (size_t)bh * MPAD * DHD;

    // Q tile (plain 16B loads)
    #pragma unroll
    for (int i = 0; i < 4; i++) {
        int e = t + i * 256;
        int q = e >> 3, c8 = (e & 7) * 8;
        *(uint4*)&s.Qs[q][c8] = *(const uint4*)&Qb[(size_t)(n0 + q) * DHD + c8];
    }
    if (t < 128) s.qm[t] = (qmask[b * NN + n0 + t] != 0u) ? 1 : 0;

    cp_k_tile_h(s, 0, Kb, 0, t);
    CP_COMMIT();
    __syncthreads();   // Qs ready for ldmatrix

    int g = lane >> 2, cl = lane & 3;
    int row_lo = w * 16 + g;
    int a_lr = lane & 15, a_lc = (lane >> 4) * 8;

    // hoisted Q A-fragments (d = 64 -> 4 k16 chunks)
    uint32_t aq[4][4];
    #pragma unroll
    for (int ko = 0; ko < 4; ko++)
        ldsm4(aq[ko], smem_u32(&s.Qs[w * 16 + a_lr][ko * 16 + a_lc]));

    float m_lo = -NEG_MAX, m_hi = -NEG_MAX, l_lo = 0.f, l_hi = 0.f;
    float oacc[8][4] = {};
    int p = 0;

    // lane maps for K (non-trans) and V (trans) B-fragments
    int k_lr = (lane & 7) + 8 * (lane >> 4);          // j-row offset within ntp*16
    int k_lc = 8 * ((lane >> 3) & 1);                 // d-col offset
    int v_lr = (lane & 7) + 8 * ((lane >> 3) & 1);    // j-row offset
    int v_lc = 8 * (lane >> 4);                       // d-col offset

    for (int kt = 0; kt < NTILES; kt++) {
        int j0 = kt * KT;
        if (t < 128) s.kb[t] = g_kbias[b * MPAD + j0 + t];

        cp_v_tile_h(s, Vb, j0, t);
        CP_COMMIT();
        if (kt < NTILES - 1) {
            cp_k_tile_h(s, 1 - p, Kb, j0 + KT, t);
            CP_COMMIT();
            CP_WAIT(2);
        } else {
            CP_WAIT(1);
        }
        __syncthreads();

        // ---- S = Q K^T ----
        float sacc[16][4] = {};
        #pragma unroll
        for (int ko = 0; ko < 4; ko++) {
            #pragma unroll
            for (int ntp = 0; ntp < 8; ntp++) {
                uint32_t bf[4];
                ldsm4(bf, smem_u32(&s.Kt[p][ntp * 16 + k_lr][ko * 16 + k_lc]));
                mma16(sacc[ntp * 2],     aq[ko], bf[0], bf[1]);
                mma16(sacc[ntp * 2 + 1], aq[ko], bf[2], bf[3]);
            }
        }

        // ---- register online softmax ----
        int qml = s.qm[row_lo], qmh = s.qm[row_lo + 8];
        float mx_lo = m_lo, mx_hi = m_hi;
        #pragma unroll
        for (int nt = 0; nt < 16; nt++) {
            float k0 = s.kb[nt * 8 + 2 * cl];
            float k1 = s.kb[nt * 8 + 2 * cl + 1];
            float x0 = (k0 == 0.f) ? (qml ? sacc[nt][0] : -NEG_MAX) : k0;
            float x1 = (k1 == 0.f) ? (qml ? sacc[nt][1] : -NEG_MAX) : k1;
            float x2 = (k0 == 0.f) ? (qmh ? sacc[nt][2] : -NEG_MAX) : k0;
            float x3 = (k1 == 0.f) ? (qmh ? sacc[nt][3] : -NEG_MAX) : k1;
            sacc[nt][0] = x0; sacc[nt][1] = x1; sacc[nt][2] = x2; sacc[nt][3] = x3;
            mx_lo = fmaxf(mx_lo, fmaxf(x0, x1));
            mx_hi = fmaxf(mx_hi, fmaxf(x2, x3));
        }
        mx_lo = fmaxf(mx_lo, __shfl_xor_sync(0xffffffffu, mx_lo, 1));
        mx_lo = fmaxf(mx_lo, __shfl_xor_sync(0xffffffffu, mx_lo, 2));
        mx_hi = fmaxf(mx_hi, __shfl_xor_sync(0xffffffffu, mx_hi, 1));
        mx_hi = fmaxf(mx_hi, __shfl_xor_sync(0xffffffffu, mx_hi, 2));

        float al_lo = __expf(m_lo - mx_lo); m_lo = mx_lo;
        float al_hi = __expf(m_hi - mx_hi); m_hi = mx_hi;

        float sum_lo = 0.f, sum_hi = 0.f;
        #pragma unroll
        for (int nt = 0; nt < 16; nt++) {
            float p0 = __expf(sacc[nt][0] - mx_lo);
            float p1 = __expf(sacc[nt][1] - mx_lo);
            float p2 = __expf(sacc[nt][2] - mx_hi);
            float p3 = __expf(sacc[nt][3] - mx_hi);
            __half2 hlo = __floats2half2_rn(p0, p1);
            __half2 hhi = __floats2half2_rn(p2, p3);
            float2 flo = __half22float2(hlo), fhi = __half22float2(hhi);
            sum_lo += flo.x + flo.y;
            sum_hi += fhi.x + fhi.y;
            int c = nt * 8 + 2 * cl;
            *(__half2*)&s.Ss[row_lo][c]     = hlo;
            *(__half2*)&s.Ss[row_lo + 8][c] = hhi;
        }
        sum_lo += __shfl_xor_sync(0xffffffffu, sum_lo, 1);
        sum_lo += __shfl_xor_sync(0xffffffffu, sum_lo, 2);
        sum_hi += __shfl_xor_sync(0xffffffffu, sum_hi, 1);
        sum_hi += __shfl_xor_sync(0xffffffffu, sum_hi, 2);
        l_lo = l_lo * al_lo + sum_lo;
        l_hi = l_hi * al_hi + sum_hi;

        if (kt < NTILES - 1) { CP_WAIT(1); } else { CP_WAIT(0); }
        __syncthreads();

        // ---- rescale + O += P V ----
        #pragma unroll
        for (int nt = 0; nt < 8; nt++) {
            oacc[nt][0] *= al_lo; oacc[nt][1] *= al_lo;
            oacc[nt][2] *= al_hi; oacc[nt][3] *= al_hi;
        }
        #pragma unroll
        for (int ko = 0; ko < 8; ko++) {
            uint32_t pa[4];
            ldsm4(pa, smem_u32(&s.Ss[w * 16 + a_lr][ko * 16 + a_lc]));
            #pragma unroll
            for (int ntp = 0; ntp < 4; ntp++) {
                uint32_t bf[4];
                ldsm4t(bf, smem_u32(&s.Vs[ko * 16 + v_lr][ntp * 16 + v_lc]));
                mma16(oacc[ntp * 2],     pa, bf[0], bf[1]);
                mma16(oacc[ntp * 2 + 1], pa, bf[2], bf[3]);
            }
        }
        __syncthreads();
        p ^= 1;
    }

    float li_lo = 1.f / l_lo, li_hi = 1.f / l_hi;
    #pragma unroll
    for (int nt = 0; nt < 8; nt++) {
        int c = nt * 8 + 2 * cl;
        size_t base_lo = ((size_t)b * NN + n0 + row_lo) * INNERD + h * DHD + c;
        size_t base_hi = ((size_t)b * NN + n0 + row_lo + 8) * INNERD + h * DHD + c;
        *(__half2*)&g_Oh[base_lo] = __floats2half2_rn(oacc[nt][0] * li_lo, oacc[nt][1] * li_lo);
        *(__half2*)&g_Oh[base_hi] = __floats2half2_rn(oacc[nt][2] * li_hi, oacc[nt][3] * li_hi);
    }
}

// ---------------------------------------------------------------------------
extern "C" void kernel_launch(void* const* d_in, const int* in_sizes, int n_in,
                              void* d_out, int out_size) {
    const float* x            = (const float*)d_in[0];
    const float* ctx          = (const float*)d_in[1];
    const unsigned int* mask  = (const unsigned int*)d_in[2];
    const unsigned int* cmask = (const unsigned int*)d_in[3];
    const float* Wq  = (const float*)d_in[4];
    const float* Wkv = (const float*)d_in[5];
    const float* Wo  = (const float*)d_in[6];
    const float* bo  = (const float*)d_in[7];
    const float* nk  = (const float*)d_in[8];
    const float* nv  = (const float*)d_in[9];
    float* out = (float*)d_out;

    static int inited = 0;
    if (!inited) {
        cudaFuncSetAttribute(attn_kernel, cudaFuncAttributeMaxDynamicSharedMemorySize,
                             (int)sizeof(AttnSmemH));
        inited = 1;
    }

    __half *xh, *ch, *wqh, *wkvh, *woh, *oh;
    cudaGetSymbolAddress((void**)&xh,   g_xh);
    cudaGetSymbolAddress((void**)&ch,   g_ch);
    cudaGetSymbolAddress((void**)&wqh,  g_wqh);
    cudaGetSymbolAddress((void**)&wkvh, g_wkvh);
    cudaGetSymbolAddress((void**)&woh,  g_woh);
    cudaGetSymbolAddress((void**)&oh,   g_Oh);

    round_h_kernel<<<(BB*NN*512/4 + 255)/256, 256>>>(x,   xh,   BB*NN*512/4);
    round_h_kernel<<<(BB*MM*512/4 + 255)/256, 256>>>(ctx, ch,   BB*MM*512/4);
    round_h_kernel<<<(512*512/4   + 255)/256, 256>>>(Wq,  wqh,  512*512/4);
    round_h_kernel<<<(512*1024/4  + 255)/256, 256>>>(Wkv, wkvh, 512*1024/4);
    round_h_kernel<<<(512*512/4   + 255)/256, 256>>>(Wo,  woh,  512*512/4);

    prep_bias_kernel<<<(BB * MPAD + 255) / 256, 256>>>(cmask);
    prep_kv_kernel<<<BB * HH, 256>>>(nk, nv);

    dim3 g0(INNERD / 128, (BB * NN) / 128);          // (4, 64)
    gemm_mma_h<<<g0, 256>>>(xh, wqh, nullptr, nullptr, INNERD, 0);

    dim3 g1((2 * INNERD) / 128, (BB * MM) / 128);    // (8, 64)
    gemm_mma_h<<<g1, 256>>>(ch, wkvh, nullptr, nullptr, 2 * INNERD, 1);

    dim3 ga(NN / QT, HH, BB);                        // (16, 8, 4)
    attn_kernel<<<ga, 256, sizeof(AttnSmemH)>>>(mask);

    dim3 g2(512 / 128, (BB * NN) / 128);             // (4, 64)
    gemm_mma_h<<<g2, 256>>>(oh, woh, bo, out, 512, 2);
}

// round 7
// speedup vs baseline: 5.8208x; 1.3142x over previous
#include <cuda_runtime.h>
#include <cuda_fp16.h>
#include <math.h>
#include <stdint.h>

#define BB 4
#define NN 2048
#define MM 2048
#define HH 8
#define DHD 64
#define INNERD 512
#define MP 2049
#define MPAD 2176          // 34 * 64
#define KT 64
#define QT 128
#define NTILES (MPAD / KT) // 34
#define NEG_MAX 3.402823466e38f

// Scratch (device globals; no allocation allowed)
__device__ __half g_Qh[(size_t)BB*HH*NN*DHD];    // [b,h,n,d]  tanh(q)*scale
__device__ __half g_Kh[(size_t)BB*HH*MPAD*DHD];  // [b,h,j,d]  tanh(k), j=0 null
__device__ __half g_Vh[(size_t)BB*HH*MPAD*DHD];  // [b,h,j,d]
__device__ __half g_Oh[(size_t)BB*NN*INNERD];    // [b,n,h*d]
__device__ float  g_kbias[BB*MPAD];              // 0 attend / -FLT_MAX masked / -INF pad
__device__ float  g_kbias2[BB*MPAD];             // 0 non-pad / -INF pad (masked-query rows)
__device__ __half g_xh[(size_t)BB*NN*512];
__device__ __half g_ch[(size_t)BB*MM*512];
__device__ __half g_wqh[512*512];
__device__ __half g_wkvh[512*1024];
__device__ __half g_woh[512*512];

__device__ __forceinline__ uint32_t smem_u32(const void* p) {
    return (uint32_t)__cvta_generic_to_shared(p);
}
__device__ __forceinline__ void ldsm4(uint32_t* r, uint32_t a) {
    asm volatile("ldmatrix.sync.aligned.m8n8.x4.shared.b16 {%0,%1,%2,%3}, [%4];"
        : "=r"(r[0]), "=r"(r[1]), "=r"(r[2]), "=r"(r[3]) : "r"(a));
}
__device__ __forceinline__ void ldsm4t(uint32_t* r, uint32_t a) {
    asm volatile("ldmatrix.sync.aligned.m8n8.x4.trans.shared.b16 {%0,%1,%2,%3}, [%4];"
        : "=r"(r[0]), "=r"(r[1]), "=r"(r[2]), "=r"(r[3]) : "r"(a));
}
__device__ __forceinline__ void mma16(float* d, const uint32_t* a, uint32_t b0, uint32_t b1) {
    asm volatile(
        "mma.sync.aligned.m16n8k16.row.col.f32.f16.f16.f32 "
        "{%0,%1,%2,%3}, {%4,%5,%6,%7}, {%8,%9}, {%0,%1,%2,%3};"
        : "+f"(d[0]), "+f"(d[1]), "+f"(d[2]), "+f"(d[3])
        : "r"(a[0]), "r"(a[1]), "r"(a[2]), "r"(a[3]), "r"(b0), "r"(b1));
}
__device__ __forceinline__ void cpa16(void* dst, const void* src) {
    uint32_t d = smem_u32(dst);
    asm volatile("cp.async.cg.shared.global [%0], [%1], 16;\n" :: "r"(d), "l"(src));
}
#define CP_COMMIT() asm volatile("cp.async.commit_group;\n" ::: "memory")
#define CP_WAIT(n)  asm volatile("cp.async.wait_group %0;\n" :: "n"(n) : "memory")

// ---------------------------------------------------------------------------
__global__ void round_h_kernel(const float* __restrict__ src, __half* __restrict__ dst, int n4) {
    int i = blockIdx.x * 256 + threadIdx.x;
    if (i >= n4) return;
    float4 v = ((const float4*)src)[i];
    __half2* d2 = (__half2*)dst;
    d2[2 * i]     = __floats2half2_rn(v.x, v.y);
    d2[2 * i + 1] = __floats2half2_rn(v.z, v.w);
}

// ---------------------------------------------------------------------------
// fp16 mma GEMM (same as R6): C[8192 x Ncols] = A[8192 x 512] @ W[512 x Ncols]
// ---------------------------------------------------------------------------
__global__ __launch_bounds__(256) void gemm_mma_h(
    const __half* __restrict__ A, const __half* __restrict__ W,
    const float* __restrict__ bias, float* __restrict__ out,
    int Ncols, int mode)
{
    __shared__ __align__(16) __half As[2][128][40];
    __shared__ __align__(16) __half Bs[2][32][136];

    int t = threadIdx.x, lane = t & 31, w = t >> 5;
    int wm = w >> 2, wn = w & 3;
    int g = lane >> 2, cl = lane & 3;
    int row0 = blockIdx.y * 128, col0 = blockIdx.x * 128;

    int ar0 = t >> 2, ac = (t & 3) * 8;
    int br0 = t >> 4, bc = (t & 15) * 8;

    float acc[4][4][4] = {};

    cpa16(&As[0][ar0][ac],      A + (size_t)(row0 + ar0) * 512 + ac);
    cpa16(&As[0][ar0 + 64][ac], A + (size_t)(row0 + ar0 + 64) * 512 + ac);
    cpa16(&Bs[0][br0][bc],      W + (size_t)br0 * Ncols + col0 + bc);
    cpa16(&Bs[0][br0 + 16][bc], W + (size_t)(br0 + 16) * Ncols + col0 + bc);
    CP_COMMIT();

    int a_lr = lane & 15, a_lc = (lane >> 4) * 8;
    int b_lr = (lane & 7) + 8 * ((lane >> 3) & 1), b_lc = 8 * (lane >> 4);

    int p = 0;
    for (int kt = 0; kt < 16; kt++) {
        if (kt < 15) {
            int k0 = (kt + 1) * 32;
            cpa16(&As[1 - p][ar0][ac],      A + (size_t)(row0 + ar0) * 512 + k0 + ac);
            cpa16(&As[1 - p][ar0 + 64][ac], A + (size_t)(row0 + ar0 + 64) * 512 + k0 + ac);
            cpa16(&Bs[1 - p][br0][bc],      W + (size_t)(k0 + br0) * Ncols + col0 + bc);
            cpa16(&Bs[1 - p][br0 + 16][bc], W + (size_t)(k0 + br0 + 16) * Ncols + col0 + bc);
            CP_COMMIT(); CP_WAIT(1);
        } else {
            CP_WAIT(0);
        }
        __syncthreads();

        #pragma unroll
        for (int kc = 0; kc < 2; kc++) {
            uint32_t af[4][4];
            #pragma unroll
            for (int mi = 0; mi < 4; mi++)
                ldsm4(af[mi], smem_u32(&As[p][wm * 64 + mi * 16 + a_lr][kc * 16 + a_lc]));
            #pragma unroll
            for (int np = 0; np < 2; np++) {
                uint32_t bf[4];
                ldsm4t(bf, smem_u32(&Bs[p][kc * 16 + b_lr][wn * 32 + np * 16 + b_lc]));
                #pragma unroll
                for (int mi = 0; mi < 4; mi++) {
                    mma16(acc[mi][np * 2],     af[mi], bf[0], bf[1]);
                    mma16(acc[mi][np * 2 + 1], af[mi], bf[2], bf[3]);
                }
            }
        }
        __syncthreads();
        p ^= 1;
    }

    int bidx = row0 >> 11;
    #pragma unroll
    for (int mi = 0; mi < 4; mi++) {
        int r0 = row0 + wm * 64 + mi * 16 + g;
        int n0r = r0 & 2047;
        #pragma unroll
        for (int ni = 0; ni < 4; ni++) {
            int c = col0 + wn * 32 + ni * 8 + 2 * cl;
            float v0 = acc[mi][ni][0], v1 = acc[mi][ni][1];
            float v2 = acc[mi][ni][2], v3 = acc[mi][ni][3];
            if (mode == 0) {
                int hh = c >> 6, d = c & 63;
                *(__half2*)&g_Qh[(((size_t)bidx * HH + hh) * NN + n0r) * DHD + d] =
                    __floats2half2_rn(tanhf(v0) * 0.125f, tanhf(v1) * 0.125f);
                *(__half2*)&g_Qh[(((size_t)bidx * HH + hh) * NN + n0r + 8) * DHD + d] =
                    __floats2half2_rn(tanhf(v2) * 0.125f, tanhf(v3) * 0.125f);
            } else if (mode == 1) {
                if (c < INNERD) {
                    int hh = c >> 6, d = c & 63;
                    *(__half2*)&g_Kh[(((size_t)bidx * HH + hh) * MPAD + n0r + 1) * DHD + d] =
                        __floats2half2_rn(tanhf(v0), tanhf(v1));
                    *(__half2*)&g_Kh[(((size_t)bidx * HH + hh) * MPAD + n0r + 9) * DHD + d] =
                        __floats2half2_rn(tanhf(v2), tanhf(v3));
                } else {
                    int c2 = c - INNERD;
                    int hh = c2 >> 6, d = c2 & 63;
                    *(__half2*)&g_Vh[(((size_t)bidx * HH + hh) * MPAD + n0r + 1) * DHD + d] =
                        __floats2half2_rn(v0, v1);
                    *(__half2*)&g_Vh[(((size_t)bidx * HH + hh) * MPAD + n0r + 9) * DHD + d] =
                        __floats2half2_rn(v2, v3);
                }
            } else {
                float b0v = bias[c], b1v = bias[c + 1];
                *(float2*)&out[(size_t)r0 * 512 + c]       = make_float2(v0 + b0v, v1 + b1v);
                *(float2*)&out[(size_t)(r0 + 8) * 512 + c] = make_float2(v2 + b0v, v3 + b1v);
            }
        }
    }
}

// ---------------------------------------------------------------------------
__global__ void prep_bias_kernel(const unsigned int* __restrict__ cmask) {
    int t = blockIdx.x * 256 + threadIdx.x;
    if (t >= BB * MPAD) return;
    int b = t / MPAD, j = t % MPAD;
    float v, v2;
    if (j == 0)        { v = 0.f; v2 = 0.f; }
    else if (j <= MM)  { v = (cmask[b * MM + (j - 1)] != 0u) ? 0.f : -NEG_MAX; v2 = 0.f; }
    else               { v = -INFINITY; v2 = -INFINITY; }
    g_kbias[t] = v;
    g_kbias2[t] = v2;
}

__global__ void prep_kv_kernel(const float* __restrict__ null_key,
                               const float* __restrict__ null_value) {
    int bh = blockIdx.x;
    __half* Kb = g_Kh + (size_t)bh * MPAD * DHD;
    __half* Vb = g_Vh + (size_t)bh * MPAD * DHD;
    int t = threadIdx.x;
    if (t < DHD) {
        Kb[t] = __float2half_rn(tanhf(null_key[t]));
        Vb[t] = __float2half_rn(null_value[t]);
    }
    for (int idx = t; idx < DHD * (MPAD - MP); idx += 256) {
        int d = idx & 63, jr = idx >> 6;
        Kb[(size_t)(MP + jr) * DHD + d] = __float2half_rn(0.f);
        Vb[(size_t)(MP + jr) * DHD + d] = __float2half_rn(0.f);
    }
}

// ---------------------------------------------------------------------------
// Flash attention: fp16 mma, register-resident P (C-frag == A-frag identity),
// 64-key tiles, 2 CTAs/SM target.
// ---------------------------------------------------------------------------
struct __align__(16) AttnSmemH {
    __half Qs[128][72];      // [q][d]
    __half Kt[2][64][72];    // [j][d] double buffered
    __half Vs[64][72];       // [j][d]
    float kb[64];
    float kbq[64];
};

__device__ __forceinline__ void cp_k_tile_h(AttnSmemH& s, int buf, const __half* Kb, int j0, int t) {
    #pragma unroll
    for (int i = 0; i < 2; i++) {
        int e = t + i * 256;
        int r = e >> 3, c8 = (e & 7) * 8;
        cpa16(&s.Kt[buf][r][c8], Kb + (size_t)(j0 + r) * DHD + c8);
    }
}
__device__ __forceinline__ void cp_v_tile_h(AttnSmemH& s, const __half* Vb, int j0, int t) {
    #pragma unroll
    for (int i = 0; i < 2; i++) {
        int e = t + i * 256;
        int r = e >> 3, c8 = (e & 7) * 8;
        cpa16(&s.Vs[r][c8], Vb + (size_t)(j0 + r) * DHD + c8);
    }
}

__global__ __launch_bounds__(256, 2) void attn_kernel(const unsigned int* __restrict__ qmask) {
    extern __shared__ char smem_raw[];
    AttnSmemH& s = *reinterpret_cast<AttnSmemH*>(smem_raw);

    int t = threadIdx.x, lane = t & 31, w = t >> 5;
    int n0 = blockIdx.x * QT;
    int h = blockIdx.y, b = blockIdx.z;
    int bh = b * HH + h;

    const __half* Qb = g_Qh + (size_t)bh * NN * DHD;
    const __half* Kb = g_Kh + (size_t)bh * MPAD * DHD;
    const __half* Vb = g_Vh + (size_t)bh * MPAD * DHD;

    // Q tile
    #pragma unroll
    for (int i = 0; i < 4; i++) {
        int e = t + i * 256;
        int q = e >> 3, c8 = (e & 7) * 8;
        *(uint4*)&s.Qs[q][c8] = *(const uint4*)&Qb[(size_t)(n0 + q) * DHD + c8];
    }
    cp_k_tile_h(s, 0, Kb, 0, t);
    CP_COMMIT();
    __syncthreads();

    int g = lane >> 2, cl = lane & 3;
    int row_lo = w * 16 + g;
    int a_lr = lane & 15, a_lc = (lane >> 4) * 8;

    uint32_t aq[4][4];
    #pragma unroll
    for (int ko = 0; ko < 4; ko++)
        ldsm4(aq[ko], smem_u32(&s.Qs[w * 16 + a_lr][ko * 16 + a_lc]));

    int qml = (qmask[b * NN + n0 + row_lo]     != 0u) ? 1 : 0;
    int qmh = (qmask[b * NN + n0 + row_lo + 8] != 0u) ? 1 : 0;

    float m_lo = -NEG_MAX, m_hi = -NEG_MAX, l_lo = 0.f, l_hi = 0.f;
    float oacc[8][4] = {};
    int p = 0;

    int k_lr = (lane & 7) + 8 * (lane >> 4);
    int k_lc = 8 * ((lane >> 3) & 1);
    int v_lr = (lane & 7) + 8 * ((lane >> 3) & 1);
    int v_lc = 8 * (lane >> 4);

    const float* kb_base  = g_kbias  + b * MPAD;
    const float* kbq_base = g_kbias2 + b * MPAD;

    for (int kt = 0; kt < NTILES; kt++) {
        int j0 = kt * KT;
        if (t < 64) {
            s.kb[t]  = kb_base[j0 + t];
            s.kbq[t] = kbq_base[j0 + t];
        }

        cp_v_tile_h(s, Vb, j0, t);
        CP_COMMIT();
        if (kt < NTILES - 1) {
            cp_k_tile_h(s, 1 - p, Kb, j0 + KT, t);
            CP_COMMIT();
            CP_WAIT(2);
        } else {
            CP_WAIT(1);
        }
        __syncthreads();

        // ---- S = Q K^T (16 x 64) ----
        float sacc[8][4] = {};
        #pragma unroll
        for (int ko = 0; ko < 4; ko++) {
            #pragma unroll
            for (int ntp = 0; ntp < 4; ntp++) {
                uint32_t bf[4];
                ldsm4(bf, smem_u32(&s.Kt[p][ntp * 16 + k_lr][ko * 16 + k_lc]));
                mma16(sacc[ntp * 2],     aq[ko], bf[0], bf[1]);
                mma16(sacc[ntp * 2 + 1], aq[ko], bf[2], bf[3]);
            }
        }

        // ---- mask + online softmax (registers only) ----
        float mx_lo = m_lo, mx_hi = m_hi;
        #pragma unroll
        for (int nt = 0; nt < 8; nt++) {
            int c = nt * 8 + 2 * cl;
            float kb0 = s.kb[c], kb1 = s.kb[c + 1];
            float kq0 = s.kbq[c], kq1 = s.kbq[c + 1];
            float x0 = qml ? sacc[nt][0] + kb0 : kq0;
            float x1 = qml ? sacc[nt][1] + kb1 : kq1;
            float x2 = qmh ? sacc[nt][2] + kb0 : kq0;
            float x3 = qmh ? sacc[nt][3] + kb1 : kq1;
            sacc[nt][0] = x0; sacc[nt][1] = x1; sacc[nt][2] = x2; sacc[nt][3] = x3;
            mx_lo = fmaxf(mx_lo, fmaxf(x0, x1));
            mx_hi = fmaxf(mx_hi, fmaxf(x2, x3));
        }
        mx_lo = fmaxf(mx_lo, __shfl_xor_sync(0xffffffffu, mx_lo, 1));
        mx_lo = fmaxf(mx_lo, __shfl_xor_sync(0xffffffffu, mx_lo, 2));
        mx_hi = fmaxf(mx_hi, __shfl_xor_sync(0xffffffffu, mx_hi, 1));
        mx_hi = fmaxf(mx_hi, __shfl_xor_sync(0xffffffffu, mx_hi, 2));

        float al_lo = __expf(m_lo - mx_lo); m_lo = mx_lo;
        float al_hi = __expf(m_hi - mx_hi); m_hi = mx_hi;

        // exp -> fp16 P-fragments (A-frag layout == C-frag layout)
        uint32_t pf_lo[8], pf_hi[8];
        float sum_lo = 0.f, sum_hi = 0.f;
        #pragma unroll
        for (int nt = 0; nt < 8; nt++) {
            float p0 = __expf(sacc[nt][0] - mx_lo);
            float p1 = __expf(sacc[nt][1] - mx_lo);
            float p2 = __expf(sacc[nt][2] - mx_hi);
            float p3 = __expf(sacc[nt][3] - mx_hi);
            __half2 hlo = __floats2half2_rn(p0, p1);
            __half2 hhi = __floats2half2_rn(p2, p3);
            float2 flo = __half22float2(hlo), fhi = __half22float2(hhi);
            sum_lo += flo.x + flo.y;
            sum_hi += fhi.x + fhi.y;
            pf_lo[nt] = *(uint32_t*)&hlo;
            pf_hi[nt] = *(uint32_t*)&hhi;
        }
        sum_lo += __shfl_xor_sync(0xffffffffu, sum_lo, 1);
        sum_lo += __shfl_xor_sync(0xffffffffu, sum_lo, 2);
        sum_hi += __shfl_xor_sync(0xffffffffu, sum_hi, 1);
        sum_hi += __shfl_xor_sync(0xffffffffu, sum_hi, 2);
        l_lo = l_lo * al_lo + sum_lo;
        l_hi = l_hi * al_hi + sum_hi;

        if (kt < NTILES - 1) { CP_WAIT(1); } else { CP_WAIT(0); }
        __syncthreads();

        // ---- rescale + O += P V ----
        #pragma unroll
        for (int nt = 0; nt < 8; nt++) {
            oacc[nt][0] *= al_lo; oacc[nt][1] *= al_lo;
            oacc[nt][2] *= al_hi; oacc[nt][3] *= al_hi;
        }
        #pragma unroll
        for (int ko2 = 0; ko2 < 4; ko2++) {
            uint32_t pa[4] = { pf_lo[ko2 * 2], pf_hi[ko2 * 2],
                               pf_lo[ko2 * 2 + 1], pf_hi[ko2 * 2 + 1] };
            #pragma unroll
            for (int ntp = 0; ntp < 4; ntp++) {
                uint32_t bf[4];
                ldsm4t(bf, smem_u32(&s.Vs[ko2 * 16 + v_lr][ntp * 16 + v_lc]));
                mma16(oacc[ntp * 2],     pa, bf[0], bf[1]);
                mma16(oacc[ntp * 2 + 1], pa, bf[2], bf[3]);
            }
        }
        __syncthreads();
        p ^= 1;
    }

    float li_lo = 1.f / l_lo, li_hi = 1.f / l_hi;
    #pragma unroll
    for (int nt = 0; nt < 8; nt++) {
        int c = nt * 8 + 2 * cl;
        size_t base_lo = ((size_t)b * NN + n0 + row_lo) * INNERD + h * DHD + c;
        size_t base_hi = ((size_t)b * NN + n0 + row_lo + 8) * INNERD + h * DHD + c;
        *(__half2*)&g_Oh[base_lo] = __floats2half2_rn(oacc[nt][0] * li_lo, oacc[nt][1] * li_lo);
        *(__half2*)&g_Oh[base_hi] = __floats2half2_rn(oacc[nt][2] * li_hi, oacc[nt][3] * li_hi);
    }
}

// ---------------------------------------------------------------------------
extern "C" void kernel_launch(void* const* d_in, const int* in_sizes, int n_in,
                              void* d_out, int out_size) {
    const float* x            = (const float*)d_in[0];
    const float* ctx          = (const float*)d_in[1];
    const unsigned int* mask  = (const unsigned int*)d_in[2];
    const unsigned int* cmask = (const unsigned int*)d_in[3];
    const float* Wq  = (const float*)d_in[4];
    const float* Wkv = (const float*)d_in[5];
    const float* Wo  = (const float*)d_in[6];
    const float* bo  = (const float*)d_in[7];
    const float* nk  = (const float*)d_in[8];
    const float* nv  = (const float*)d_in[9];
    float* out = (float*)d_out;

    static int inited = 0;
    if (!inited) {
        cudaFuncSetAttribute(attn_kernel, cudaFuncAttributeMaxDynamicSharedMemorySize,
                             (int)sizeof(AttnSmemH));
        inited = 1;
    }

    __half *xh, *ch, *wqh, *wkvh, *woh, *oh;
    cudaGetSymbolAddress((void**)&xh,   g_xh);
    cudaGetSymbolAddress((void**)&ch,   g_ch);
    cudaGetSymbolAddress((void**)&wqh,  g_wqh);
    cudaGetSymbolAddress((void**)&wkvh, g_wkvh);
    cudaGetSymbolAddress((void**)&woh,  g_woh);
    cudaGetSymbolAddress((void**)&oh,   g_Oh);

    round_h_kernel<<<(BB*NN*512/4 + 255)/256, 256>>>(x,   xh,   BB*NN*512/4);
    round_h_kernel<<<(BB*MM*512/4 + 255)/256, 256>>>(ctx, ch,   BB*MM*512/4);
    round_h_kernel<<<(512*512/4   + 255)/256, 256>>>(Wq,  wqh,  512*512/4);
    round_h_kernel<<<(512*1024/4  + 255)/256, 256>>>(Wkv, wkvh, 512*1024/4);
    round_h_kernel<<<(512*512/4   + 255)/256, 256>>>(Wo,  woh,  512*512/4);

    prep_bias_kernel<<<(BB * MPAD + 255) / 256, 256>>>(cmask);
    prep_kv_kernel<<<BB * HH, 256>>>(nk, nv);

    dim3 g0(INNERD / 128, (BB * NN) / 128);          // (4, 64)
    gemm_mma_h<<<g0, 256>>>(xh, wqh, nullptr, nullptr, INNERD, 0);

    dim3 g1((2 * INNERD) / 128, (BB * MM) / 128);    // (8, 64)
    gemm_mma_h<<<g1, 256>>>(ch, wkvh, nullptr, nullptr, 2 * INNERD, 1);

    dim3 ga(NN / QT, HH, BB);                        // (16, 8, 4)
    attn_kernel<<<ga, 256, sizeof(AttnSmemH)>>>(mask);

    dim3 g2(512 / 128, (BB * NN) / 128);             // (4, 64)
    gemm_mma_h<<<g2, 256>>>(oh, woh, bo, out, 512, 2);
}

// round 8
// speedup vs baseline: 6.2509x; 1.0739x over previous
#include <cuda_runtime.h>
#include <cuda_fp16.h>
#include <math.h>
#include <stdint.h>

#define BB 4
#define NN 2048
#define MM 2048
#define HH 8
#define DHD 64
#define INNERD 512
#define MP 2049
#define MPAD 2176          // 34 * 64
#define KT 64
#define QT 128
#define NTILES (MPAD / KT) // 34
#define NEG_MAX 3.402823466e38f

// Scratch (device globals; no allocation allowed)
__device__ __half g_Qh[(size_t)BB*HH*NN*DHD];    // [b,h,n,d]  tanh(q)*scale
__device__ __half g_Kh[(size_t)BB*HH*MPAD*DHD];  // [b,h,j,d]  tanh(k), j=0 null
__device__ __half g_Vh[(size_t)BB*HH*MPAD*DHD];  // [b,h,j,d]
__device__ __half g_Oh[(size_t)BB*NN*INNERD];    // [b,n,h*d]
__device__ float  g_kbias[BB*MPAD];              // 0 attend / -FLT_MAX masked / -INF pad
__device__ float  g_kbias2[BB*MPAD];             // 0 non-pad / -INF pad (masked-query rows)
__device__ __half g_xh[(size_t)BB*NN*512];
__device__ __half g_ch[(size_t)BB*MM*512];
__device__ __half g_wqh[512*512];
__device__ __half g_wkvh[512*1024];
__device__ __half g_woh[512*512];

__device__ __forceinline__ uint32_t smem_u32(const void* p) {
    return (uint32_t)__cvta_generic_to_shared(p);
}
__device__ __forceinline__ void ldsm4(uint32_t* r, uint32_t a) {
    asm volatile("ldmatrix.sync.aligned.m8n8.x4.shared.b16 {%0,%1,%2,%3}, [%4];"
        : "=r"(r[0]), "=r"(r[1]), "=r"(r[2]), "=r"(r[3]) : "r"(a));
}
__device__ __forceinline__ void ldsm4t(uint32_t* r, uint32_t a) {
    asm volatile("ldmatrix.sync.aligned.m8n8.x4.trans.shared.b16 {%0,%1,%2,%3}, [%4];"
        : "=r"(r[0]), "=r"(r[1]), "=r"(r[2]), "=r"(r[3]) : "r"(a));
}
__device__ __forceinline__ void mma16(float* d, const uint32_t* a, uint32_t b0, uint32_t b1) {
    asm volatile(
        "mma.sync.aligned.m16n8k16.row.col.f32.f16.f16.f32 "
        "{%0,%1,%2,%3}, {%4,%5,%6,%7}, {%8,%9}, {%0,%1,%2,%3};"
        : "+f"(d[0]), "+f"(d[1]), "+f"(d[2]), "+f"(d[3])
        : "r"(a[0]), "r"(a[1]), "r"(a[2]), "r"(a[3]), "r"(b0), "r"(b1));
}
__device__ __forceinline__ void cpa16(void* dst, const void* src) {
    uint32_t d = smem_u32(dst);
    asm volatile("cp.async.cg.shared.global [%0], [%1], 16;\n" :: "r"(d), "l"(src));
}
#define CP_COMMIT() asm volatile("cp.async.commit_group;\n" ::: "memory")
#define CP_WAIT(n)  asm volatile("cp.async.wait_group %0;\n" :: "n"(n) : "memory")

// ---------------------------------------------------------------------------
// Fused fp32 -> fp16 round (RN) for all five inputs in one launch
// ---------------------------------------------------------------------------
#define N4_X   (BB*NN*512/4)
#define N4_C   (BB*MM*512/4)
#define N4_WQ  (512*512/4)
#define N4_WKV (512*1024/4)
#define N4_WO  (512*512/4)
#define N4_TOT (N4_X + N4_C + N4_WQ + N4_WKV + N4_WO)

__global__ void round_all_kernel(const float* __restrict__ x, const float* __restrict__ ctx,
                                 const float* __restrict__ wq, const float* __restrict__ wkv,
                                 const float* __restrict__ wo) {
    int i = blockIdx.x * 256 + threadIdx.x;
    if (i >= N4_TOT) return;
    const float* src; __half* dst; int off;
    if (i < N4_X)                      { src = x;   dst = g_xh;   off = i; }
    else if (i < N4_X + N4_C)          { src = ctx; dst = g_ch;   off = i - N4_X; }
    else if (i < N4_X + N4_C + N4_WQ)  { src = wq;  dst = g_wqh;  off = i - N4_X - N4_C; }
    else if (i < N4_X + N4_C + N4_WQ + N4_WKV)
                                       { src = wkv; dst = g_wkvh; off = i - N4_X - N4_C - N4_WQ; }
    else                               { src = wo;  dst = g_woh;  off = i - N4_X - N4_C - N4_WQ - N4_WKV; }
    float4 v = ((const float4*)src)[off];
    __half2* d2 = (__half2*)dst;
    d2[2 * off]     = __floats2half2_rn(v.x, v.y);
    d2[2 * off + 1] = __floats2half2_rn(v.z, v.w);
}

// ---------------------------------------------------------------------------
// fp16 mma GEMM: C[8192 x Ncols] = A[8192 x 512] @ W[512 x Ncols], fp32 accum
// Block 128x128, 8 warps (2x4), warp tile 64x32, k-chunk 32, dbl buf, 2 CTA/SM
// ---------------------------------------------------------------------------
__global__ __launch_bounds__(256, 2) void gemm_mma_h(
    const __half* __restrict__ A, const __half* __restrict__ W,
    const float* __restrict__ bias, float* __restrict__ out,
    int Ncols, int mode)
{
    __shared__ __align__(16) __half As[2][128][40];
    __shared__ __align__(16) __half Bs[2][32][136];

    int t = threadIdx.x, lane = t & 31, w = t >> 5;
    int wm = w >> 2, wn = w & 3;
    int g = lane >> 2, cl = lane & 3;
    int row0 = blockIdx.y * 128, col0 = blockIdx.x * 128;

    int ar0 = t >> 2, ac = (t & 3) * 8;
    int br0 = t >> 4, bc = (t & 15) * 8;

    float acc[4][4][4] = {};

    cpa16(&As[0][ar0][ac],      A + (size_t)(row0 + ar0) * 512 + ac);
    cpa16(&As[0][ar0 + 64][ac], A + (size_t)(row0 + ar0 + 64) * 512 + ac);
    cpa16(&Bs[0][br0][bc],      W + (size_t)br0 * Ncols + col0 + bc);
    cpa16(&Bs[0][br0 + 16][bc], W + (size_t)(br0 + 16) * Ncols + col0 + bc);
    CP_COMMIT();

    int a_lr = lane & 15, a_lc = (lane >> 4) * 8;
    int b_lr = (lane & 7) + 8 * ((lane >> 3) & 1), b_lc = 8 * (lane >> 4);

    int p = 0;
    for (int kt = 0; kt < 16; kt++) {
        if (kt < 15) {
            int k0 = (kt + 1) * 32;
            cpa16(&As[1 - p][ar0][ac],      A + (size_t)(row0 + ar0) * 512 + k0 + ac);
            cpa16(&As[1 - p][ar0 + 64][ac], A + (size_t)(row0 + ar0 + 64) * 512 + k0 + ac);
            cpa16(&Bs[1 - p][br0][bc],      W + (size_t)(k0 + br0) * Ncols + col0 + bc);
            cpa16(&Bs[1 - p][br0 + 16][bc], W + (size_t)(k0 + br0 + 16) * Ncols + col0 + bc);
            CP_COMMIT(); CP_WAIT(1);
        } else {
            CP_WAIT(0);
        }
        __syncthreads();

        #pragma unroll
        for (int kc = 0; kc < 2; kc++) {
            uint32_t af[4][4];
            #pragma unroll
            for (int mi = 0; mi < 4; mi++)
                ldsm4(af[mi], smem_u32(&As[p][wm * 64 + mi * 16 + a_lr][kc * 16 + a_lc]));
            #pragma unroll
            for (int np = 0; np < 2; np++) {
                uint32_t bf[4];
                ldsm4t(bf, smem_u32(&Bs[p][kc * 16 + b_lr][wn * 32 + np * 16 + b_lc]));
                #pragma unroll
                for (int mi = 0; mi < 4; mi++) {
                    mma16(acc[mi][np * 2],     af[mi], bf[0], bf[1]);
                    mma16(acc[mi][np * 2 + 1], af[mi], bf[2], bf[3]);
                }
            }
        }
        __syncthreads();
        p ^= 1;
    }

    int bidx = row0 >> 11;
    #pragma unroll
    for (int mi = 0; mi < 4; mi++) {
        int r0 = row0 + wm * 64 + mi * 16 + g;
        int n0r = r0 & 2047;
        #pragma unroll
        for (int ni = 0; ni < 4; ni++) {
            int c = col0 + wn * 32 + ni * 8 + 2 * cl;
            float v0 = acc[mi][ni][0], v1 = acc[mi][ni][1];
            float v2 = acc[mi][ni][2], v3 = acc[mi][ni][3];
            if (mode == 0) {
                int hh = c >> 6, d = c & 63;
                *(__half2*)&g_Qh[(((size_t)bidx * HH + hh) * NN + n0r) * DHD + d] =
                    __floats2half2_rn(tanhf(v0) * 0.125f, tanhf(v1) * 0.125f);
                *(__half2*)&g_Qh[(((size_t)bidx * HH + hh) * NN + n0r + 8) * DHD + d] =
                    __floats2half2_rn(tanhf(v2) * 0.125f, tanhf(v3) * 0.125f);
            } else if (mode == 1) {
                if (c < INNERD) {
                    int hh = c >> 6, d = c & 63;
                    *(__half2*)&g_Kh[(((size_t)bidx * HH + hh) * MPAD + n0r + 1) * DHD + d] =
                        __floats2half2_rn(tanhf(v0), tanhf(v1));
                    *(__half2*)&g_Kh[(((size_t)bidx * HH + hh) * MPAD + n0r + 9) * DHD + d] =
                        __floats2half2_rn(tanhf(v2), tanhf(v3));
                } else {
                    int c2 = c - INNERD;
                    int hh = c2 >> 6, d = c2 & 63;
                    *(__half2*)&g_Vh[(((size_t)bidx * HH + hh) * MPAD + n0r + 1) * DHD + d] =
                        __floats2half2_rn(v0, v1);
                    *(__half2*)&g_Vh[(((size_t)bidx * HH + hh) * MPAD + n0r + 9) * DHD + d] =
                        __floats2half2_rn(v2, v3);
                }
            } else {
                float b0v = bias[c], b1v = bias[c + 1];
                *(float2*)&out[(size_t)r0 * 512 + c]       = make_float2(v0 + b0v, v1 + b1v);
                *(float2*)&out[(size_t)(r0 + 8) * 512 + c] = make_float2(v2 + b0v, v3 + b1v);
            }
        }
    }
}

// ---------------------------------------------------------------------------
__global__ void prep_bias_kernel(const unsigned int* __restrict__ cmask) {
    int t = blockIdx.x * 256 + threadIdx.x;
    if (t >= BB * MPAD) return;
    int b = t / MPAD, j = t % MPAD;
    float v, v2;
    if (j == 0)        { v = 0.f; v2 = 0.f; }
    else if (j <= MM)  { v = (cmask[b * MM + (j - 1)] != 0u) ? 0.f : -NEG_MAX; v2 = 0.f; }
    else               { v = -INFINITY; v2 = -INFINITY; }
    g_kbias[t] = v;
    g_kbias2[t] = v2;
}

__global__ void prep_kv_kernel(const float* __restrict__ null_key,
                               const float* __restrict__ null_value) {
    int bh = blockIdx.x;
    __half* Kb = g_Kh + (size_t)bh * MPAD * DHD;
    __half* Vb = g_Vh + (size_t)bh * MPAD * DHD;
    int t = threadIdx.x;
    if (t < DHD) {
        Kb[t] = __float2half_rn(tanhf(null_key[t]));
        Vb[t] = __float2half_rn(null_value[t]);
    }
    for (int idx = t; idx < DHD * (MPAD - MP); idx += 256) {
        int d = idx & 63, jr = idx >> 6;
        Kb[(size_t)(MP + jr) * DHD + d] = __float2half_rn(0.f);
        Vb[(size_t)(MP + jr) * DHD + d] = __float2half_rn(0.f);
    }
}

// ---------------------------------------------------------------------------
// Flash attention: fp16 mma, register-resident P, 64-key tiles, 2 CTAs/SM.
// ---------------------------------------------------------------------------
struct __align__(16) AttnSmemH {
    __half Qs[128][72];      // [q][d]
    __half Kt[2][64][72];    // [j][d] double buffered
    __half Vs[64][72];       // [j][d]
    float kb[64];
    float kbq[64];
};

__device__ __forceinline__ void cp_k_tile_h(AttnSmemH& s, int buf, const __half* Kb, int j0, int t) {
    #pragma unroll
    for (int i = 0; i < 2; i++) {
        int e = t + i * 256;
        int r = e >> 3, c8 = (e & 7) * 8;
        cpa16(&s.Kt[buf][r][c8], Kb + (size_t)(j0 + r) * DHD + c8);
    }
}
__device__ __forceinline__ void cp_v_tile_h(AttnSmemH& s, const __half* Vb, int j0, int t) {
    #pragma unroll
    for (int i = 0; i < 2; i++) {
        int e = t + i * 256;
        int r = e >> 3, c8 = (e & 7) * 8;
        cpa16(&s.Vs[r][c8], Vb + (size_t)(j0 + r) * DHD + c8);
    }
}

__global__ __launch_bounds__(256, 2) void attn_kernel(const unsigned int* __restrict__ qmask) {
    extern __shared__ char smem_raw[];
    AttnSmemH& s = *reinterpret_cast<AttnSmemH*>(smem_raw);

    int t = threadIdx.x, lane = t & 31, w = t >> 5;
    int n0 = blockIdx.x * QT;
    int h = blockIdx.y, b = blockIdx.z;
    int bh = b * HH + h;

    const __half* Qb = g_Qh + (size_t)bh * NN * DHD;
    const __half* Kb = g_Kh + (size_t)bh * MPAD * DHD;
    const __half* Vb = g_Vh + (size_t)bh * MPAD * DHD;

    #pragma unroll
    for (int i = 0; i < 4; i++) {
        int e = t + i * 256;
        int q = e >> 3, c8 = (e & 7) * 8;
        *(uint4*)&s.Qs[q][c8] = *(const uint4*)&Qb[(size_t)(n0 + q) * DHD + c8];
    }
    cp_k_tile_h(s, 0, Kb, 0, t);
    CP_COMMIT();
    __syncthreads();

    int g = lane >> 2, cl = lane & 3;
    int row_lo = w * 16 + g;
    int a_lr = lane & 15, a_lc = (lane >> 4) * 8;

    uint32_t aq[4][4];
    #pragma unroll
    for (int ko = 0; ko < 4; ko++)
        ldsm4(aq[ko], smem_u32(&s.Qs[w * 16 + a_lr][ko * 16 + a_lc]));

    int qml = (qmask[b * NN + n0 + row_lo]     != 0u) ? 1 : 0;
    int qmh = (qmask[b * NN + n0 + row_lo + 8] != 0u) ? 1 : 0;

    float m_lo = -NEG_MAX, m_hi = -NEG_MAX, l_lo = 0.f, l_hi = 0.f;
    float oacc[8][4] = {};
    int p = 0;

    int k_lr = (lane & 7) + 8 * (lane >> 4);
    int k_lc = 8 * ((lane >> 3) & 1);
    int v_lr = (lane & 7) + 8 * ((lane >> 3) & 1);
    int v_lc = 8 * (lane >> 4);

    const float* kb_base  = g_kbias  + b * MPAD;
    const float* kbq_base = g_kbias2 + b * MPAD;

    for (int kt = 0; kt < NTILES; kt++) {
        int j0 = kt * KT;
        if (t < 64) {
            s.kb[t]  = kb_base[j0 + t];
            s.kbq[t] = kbq_base[j0 + t];
        }

        cp_v_tile_h(s, Vb, j0, t);
        CP_COMMIT();
        if (kt < NTILES - 1) {
            cp_k_tile_h(s, 1 - p, Kb, j0 + KT, t);
            CP_COMMIT();
            CP_WAIT(2);
        } else {
            CP_WAIT(1);
        }
        __syncthreads();

        // ---- S = Q K^T ----
        float sacc[8][4] = {};
        #pragma unroll
        for (int ko = 0; ko < 4; ko++) {
            #pragma unroll
            for (int ntp = 0; ntp < 4; ntp++) {
                uint32_t bf[4];
                ldsm4(bf, smem_u32(&s.Kt[p][ntp * 16 + k_lr][ko * 16 + k_lc]));
                mma16(sacc[ntp * 2],     aq[ko], bf[0], bf[1]);
                mma16(sacc[ntp * 2 + 1], aq[ko], bf[2], bf[3]);
            }
        }

        // ---- mask + online softmax ----
        float mx_lo = m_lo, mx_hi = m_hi;
        #pragma unroll
        for (int nt = 0; nt < 8; nt++) {
            int c = nt * 8 + 2 * cl;
            float kb0 = s.kb[c], kb1 = s.kb[c + 1];
            float kq0 = s.kbq[c], kq1 = s.kbq[c + 1];
            float x0 = qml ? sacc[nt][0] + kb0 : kq0;
            float x1 = qml ? sacc[nt][1] + kb1 : kq1;
            float x2 = qmh ? sacc[nt][2] + kb0 : kq0;
            float x3 = qmh ? sacc[nt][3] + kb1 : kq1;
            sacc[nt][0] = x0; sacc[nt][1] = x1; sacc[nt][2] = x2; sacc[nt][3] = x3;
            mx_lo = fmaxf(mx_lo, fmaxf(x0, x1));
            mx_hi = fmaxf(mx_hi, fmaxf(x2, x3));
        }
        mx_lo = fmaxf(mx_lo, __shfl_xor_sync(0xffffffffu, mx_lo, 1));
        mx_lo = fmaxf(mx_lo, __shfl_xor_sync(0xffffffffu, mx_lo, 2));
        mx_hi = fmaxf(mx_hi, __shfl_xor_sync(0xffffffffu, mx_hi, 1));
        mx_hi = fmaxf(mx_hi, __shfl_xor_sync(0xffffffffu, mx_hi, 2));

        float al_lo = __expf(m_lo - mx_lo); m_lo = mx_lo;
        float al_hi = __expf(m_hi - mx_hi); m_hi = mx_hi;

        uint32_t pf_lo[8], pf_hi[8];
        float sum_lo = 0.f, sum_hi = 0.f;
        #pragma unroll
        for (int nt = 0; nt < 8; nt++) {
            float p0 = __expf(sacc[nt][0] - mx_lo);
            float p1 = __expf(sacc[nt][1] - mx_lo);
            float p2 = __expf(sacc[nt][2] - mx_hi);
            float p3 = __expf(sacc[nt][3] - mx_hi);
            __half2 hlo = __floats2half2_rn(p0, p1);
            __half2 hhi = __floats2half2_rn(p2, p3);
            float2 flo = __half22float2(hlo), fhi = __half22float2(hhi);
            sum_lo += flo.x + flo.y;
            sum_hi += fhi.x + fhi.y;
            pf_lo[nt] = *(uint32_t*)&hlo;
            pf_hi[nt] = *(uint32_t*)&hhi;
        }
        sum_lo += __shfl_xor_sync(0xffffffffu, sum_lo, 1);
        sum_lo += __shfl_xor_sync(0xffffffffu, sum_lo, 2);
        sum_hi += __shfl_xor_sync(0xffffffffu, sum_hi, 1);
        sum_hi += __shfl_xor_sync(0xffffffffu, sum_hi, 2);
        l_lo = l_lo * al_lo + sum_lo;
        l_hi = l_hi * al_hi + sum_hi;

        if (kt < NTILES - 1) { CP_WAIT(1); } else { CP_WAIT(0); }
        __syncthreads();

        // ---- rescale + O += P V ----
        #pragma unroll
        for (int nt = 0; nt < 8; nt++) {
            oacc[nt][0] *= al_lo; oacc[nt][1] *= al_lo;
            oacc[nt][2] *= al_hi; oacc[nt][3] *= al_hi;
        }
        #pragma unroll
        for (int ko2 = 0; ko2 < 4; ko2++) {
            uint32_t pa[4] = { pf_lo[ko2 * 2], pf_hi[ko2 * 2],
                               pf_lo[ko2 * 2 + 1], pf_hi[ko2 * 2 + 1] };
            #pragma unroll
            for (int ntp = 0; ntp < 4; ntp++) {
                uint32_t bf[4];
                ldsm4t(bf, smem_u32(&s.Vs[ko2 * 16 + v_lr][ntp * 16 + v_lc]));
                mma16(oacc[ntp * 2],     pa, bf[0], bf[1]);
                mma16(oacc[ntp * 2 + 1], pa, bf[2], bf[3]);
            }
        }
        __syncthreads();
        p ^= 1;
    }

    float li_lo = 1.f / l_lo, li_hi = 1.f / l_hi;
    #pragma unroll
    for (int nt = 0; nt < 8; nt++) {
        int c = nt * 8 + 2 * cl;
        size_t base_lo = ((size_t)b * NN + n0 + row_lo) * INNERD + h * DHD + c;
        size_t base_hi = ((size_t)b * NN + n0 + row_lo + 8) * INNERD + h * DHD + c;
        *(__half2*)&g_Oh[base_lo] = __floats2half2_rn(oacc[nt][0] * li_lo, oacc[nt][1] * li_lo);
        *(__half2*)&g_Oh[base_hi] = __floats2half2_rn(oacc[nt][2] * li_hi, oacc[nt][3] * li_hi);
    }
}

// ---------------------------------------------------------------------------
extern "C" void kernel_launch(void* const* d_in, const int* in_sizes, int n_in,
                              void* d_out, int out_size) {
    const float* x            = (const float*)d_in[0];
    const float* ctx          = (const float*)d_in[1];
    const unsigned int* mask  = (const unsigned int*)d_in[2];
    const unsigned int* cmask = (const unsigned int*)d_in[3];
    const float* Wq  = (const float*)d_in[4];
    const float* Wkv = (const float*)d_in[5];
    const float* Wo  = (const float*)d_in[6];
    const float* bo  = (const float*)d_in[7];
    const float* nk  = (const float*)d_in[8];
    const float* nv  = (const float*)d_in[9];
    float* out = (float*)d_out;

    static int inited = 0;
    if (!inited) {
        cudaFuncSetAttribute(attn_kernel, cudaFuncAttributeMaxDynamicSharedMemorySize,
                             (int)sizeof(AttnSmemH));
        inited = 1;
    }

    __half *xh, *ch, *wqh, *wkvh, *woh, *oh;
    cudaGetSymbolAddress((void**)&xh,   g_xh);
    cudaGetSymbolAddress((void**)&ch,   g_ch);
    cudaGetSymbolAddress((void**)&wqh,  g_wqh);
    cudaGetSymbolAddress((void**)&wkvh, g_wkvh);
    cudaGetSymbolAddress((void**)&woh,  g_woh);
    cudaGetSymbolAddress((void**)&oh,   g_Oh);

    round_all_kernel<<<(N4_TOT + 255) / 256, 256>>>(x, ctx, Wq, Wkv, Wo);

    prep_bias_kernel<<<(BB * MPAD + 255) / 256, 256>>>(cmask);
    prep_kv_kernel<<<BB * HH, 256>>>(nk, nv);

    dim3 g0(INNERD / 128, (BB * NN) / 128);          // (4, 64)
    gemm_mma_h<<<g0, 256>>>(xh, wqh, nullptr, nullptr, INNERD, 0);

    dim3 g1((2 * INNERD) / 128, (BB * MM) / 128);    // (8, 64)
    gemm_mma_h<<<g1, 256>>>(ch, wkvh, nullptr, nullptr, 2 * INNERD, 1);

    dim3 ga(NN / QT, HH, BB);                        // (16, 8, 4)
    attn_kernel<<<ga, 256, sizeof(AttnSmemH)>>>(mask);

    dim3 g2(512 / 128, (BB * NN) / 128);             // (4, 64)
    gemm_mma_h<<<g2, 256>>>(oh, woh, bo, out, 512, 2);
}

// round 9
// speedup vs baseline: 6.4776x; 1.0363x over previous
#include <cuda_runtime.h>
#include <cuda_fp16.h>
#include <math.h>
#include <stdint.h>

#define BB 4
#define NN 2048
#define MM 2048
#define HH 8
#define DHD 64
#define INNERD 512
#define MP 2049
#define MPAD 2176          // 34 * 64
#define KT 64
#define QT 128
#define NTILES (MPAD / KT) // 34
#define NEG_MAX 3.402823466e38f

// Scratch (device globals; no allocation allowed)
__device__ __half g_Qh[(size_t)BB*HH*NN*DHD];    // [b,h,n,d]  tanh(q)*scale
__device__ __half g_Kh[(size_t)BB*HH*MPAD*DHD];  // [b,h,j,d]  tanh(k), j=0 null
__device__ __half g_Vh[(size_t)BB*HH*MPAD*DHD];  // [b,h,j,d]
__device__ __half g_Oh[(size_t)BB*NN*INNERD];    // [b,n,h*d]
__device__ float  g_kbias[BB*MPAD];              // 0 attend / -FLT_MAX masked / -INF pad
__device__ float  g_kbias2[BB*MPAD];             // 0 non-pad / -INF pad (masked-query rows)
__device__ __half g_xh[(size_t)BB*NN*512];
__device__ __half g_ch[(size_t)BB*MM*512];
__device__ __half g_wqh[512*512];
__device__ __half g_wkvh[512*1024];
__device__ __half g_woh[512*512];

__device__ __forceinline__ uint32_t smem_u32(const void* p) {
    return (uint32_t)__cvta_generic_to_shared(p);
}
__device__ __forceinline__ void ldsm4(uint32_t* r, uint32_t a) {
    asm volatile("ldmatrix.sync.aligned.m8n8.x4.shared.b16 {%0,%1,%2,%3}, [%4];"
        : "=r"(r[0]), "=r"(r[1]), "=r"(r[2]), "=r"(r[3]) : "r"(a));
}
__device__ __forceinline__ void ldsm4t(uint32_t* r, uint32_t a) {
    asm volatile("ldmatrix.sync.aligned.m8n8.x4.trans.shared.b16 {%0,%1,%2,%3}, [%4];"
        : "=r"(r[0]), "=r"(r[1]), "=r"(r[2]), "=r"(r[3]) : "r"(a));
}
__device__ __forceinline__ void mma16(float* d, const uint32_t* a, uint32_t b0, uint32_t b1) {
    asm volatile(
        "mma.sync.aligned.m16n8k16.row.col.f32.f16.f16.f32 "
        "{%0,%1,%2,%3}, {%4,%5,%6,%7}, {%8,%9}, {%0,%1,%2,%3};"
        : "+f"(d[0]), "+f"(d[1]), "+f"(d[2]), "+f"(d[3])
        : "r"(a[0]), "r"(a[1]), "r"(a[2]), "r"(a[3]), "r"(b0), "r"(b1));
}
__device__ __forceinline__ void cpa16(void* dst, const void* src) {
    uint32_t d = smem_u32(dst);
    asm volatile("cp.async.cg.shared.global [%0], [%1], 16;\n" :: "r"(d), "l"(src));
}
#define CP_COMMIT() asm volatile("cp.async.commit_group;\n" ::: "memory")
#define CP_WAIT(n)  asm volatile("cp.async.wait_group %0;\n" :: "n"(n) : "memory")

// ---------------------------------------------------------------------------
// Fused fp32 -> fp16 round (RN) for all five inputs in one launch
// ---------------------------------------------------------------------------
#define N4_X   (BB*NN*512/4)
#define N4_C   (BB*MM*512/4)
#define N4_WQ  (512*512/4)
#define N4_WKV (512*1024/4)
#define N4_WO  (512*512/4)
#define N4_TOT (N4_X + N4_C + N4_WQ + N4_WKV + N4_WO)

__global__ void round_all_kernel(const float* __restrict__ x, const float* __restrict__ ctx,
                                 const float* __restrict__ wq, const float* __restrict__ wkv,
                                 const float* __restrict__ wo) {
    int i = blockIdx.x * 256 + threadIdx.x;
    if (i >= N4_TOT) return;
    const float* src; __half* dst; int off;
    if (i < N4_X)                      { src = x;   dst = g_xh;   off = i; }
    else if (i < N4_X + N4_C)          { src = ctx; dst = g_ch;   off = i - N4_X; }
    else if (i < N4_X + N4_C + N4_WQ)  { src = wq;  dst = g_wqh;  off = i - N4_X - N4_C; }
    else if (i < N4_X + N4_C + N4_WQ + N4_WKV)
                                       { src = wkv; dst = g_wkvh; off = i - N4_X - N4_C - N4_WQ; }
    else                               { src = wo;  dst = g_woh;  off = i - N4_X - N4_C - N4_WQ - N4_WKV; }
    float4 v = ((const float4*)src)[off];
    __half2* d2 = (__half2*)dst;
    d2[2 * off]     = __floats2half2_rn(v.x, v.y);
    d2[2 * off + 1] = __floats2half2_rn(v.z, v.w);
}

// ---------------------------------------------------------------------------
// fp16 mma GEMM. mode 0: Q proj; 1: KV proj; 2: O proj; 3: fused Q+KV dispatch
// ---------------------------------------------------------------------------
__global__ __launch_bounds__(256, 2) void gemm_mma_h(
    const __half* __restrict__ A, const __half* __restrict__ W,
    const float* __restrict__ bias, float* __restrict__ out,
    int Ncols, int mode)
{
    __shared__ __align__(16) __half As[2][128][40];
    __shared__ __align__(16) __half Bs[2][32][136];

    int t = threadIdx.x, lane = t & 31, w = t >> 5;
    int wm = w >> 2, wn = w & 3;
    int g = lane >> 2, cl = lane & 3;
    int row0 = blockIdx.y * 128;
    int col0;
    if (mode == 3) {
        if (blockIdx.x < 4) { A = g_xh; W = g_wqh;  Ncols = 512;  mode = 0; col0 = blockIdx.x * 128; }
        else                { A = g_ch; W = g_wkvh; Ncols = 1024; mode = 1; col0 = (blockIdx.x - 4) * 128; }
    } else {
        col0 = blockIdx.x * 128;
    }

    int ar0 = t >> 2, ac = (t & 3) * 8;
    int br0 = t >> 4, bc = (t & 15) * 8;

    float acc[4][4][4] = {};

    cpa16(&As[0][ar0][ac],      A + (size_t)(row0 + ar0) * 512 + ac);
    cpa16(&As[0][ar0 + 64][ac], A + (size_t)(row0 + ar0 + 64) * 512 + ac);
    cpa16(&Bs[0][br0][bc],      W + (size_t)br0 * Ncols + col0 + bc);
    cpa16(&Bs[0][br0 + 16][bc], W + (size_t)(br0 + 16) * Ncols + col0 + bc);
    CP_COMMIT();

    int a_lr = lane & 15, a_lc = (lane >> 4) * 8;
    int b_lr = (lane & 7) + 8 * ((lane >> 3) & 1), b_lc = 8 * (lane >> 4);

    int p = 0;
    for (int kt = 0; kt < 16; kt++) {
        if (kt < 15) {
            int k0 = (kt + 1) * 32;
            cpa16(&As[1 - p][ar0][ac],      A + (size_t)(row0 + ar0) * 512 + k0 + ac);
            cpa16(&As[1 - p][ar0 + 64][ac], A + (size_t)(row0 + ar0 + 64) * 512 + k0 + ac);
            cpa16(&Bs[1 - p][br0][bc],      W + (size_t)(k0 + br0) * Ncols + col0 + bc);
            cpa16(&Bs[1 - p][br0 + 16][bc], W + (size_t)(k0 + br0 + 16) * Ncols + col0 + bc);
            CP_COMMIT(); CP_WAIT(1);
        } else {
            CP_WAIT(0);
        }
        __syncthreads();

        #pragma unroll
        for (int kc = 0; kc < 2; kc++) {
            uint32_t af[4][4];
            #pragma unroll
            for (int mi = 0; mi < 4; mi++)
                ldsm4(af[mi], smem_u32(&As[p][wm * 64 + mi * 16 + a_lr][kc * 16 + a_lc]));
            #pragma unroll
            for (int np = 0; np < 2; np++) {
                uint32_t bf[4];
                ldsm4t(bf, smem_u32(&Bs[p][kc * 16 + b_lr][wn * 32 + np * 16 + b_lc]));
                #pragma unroll
                for (int mi = 0; mi < 4; mi++) {
                    mma16(acc[mi][np * 2],     af[mi], bf[0], bf[1]);
                    mma16(acc[mi][np * 2 + 1], af[mi], bf[2], bf[3]);
                }
            }
        }
        __syncthreads();
        p ^= 1;
    }

    int bidx = row0 >> 11;
    #pragma unroll
    for (int mi = 0; mi < 4; mi++) {
        int r0 = row0 + wm * 64 + mi * 16 + g;
        int n0r = r0 & 2047;
        #pragma unroll
        for (int ni = 0; ni < 4; ni++) {
            int c = col0 + wn * 32 + ni * 8 + 2 * cl;
            float v0 = acc[mi][ni][0], v1 = acc[mi][ni][1];
            float v2 = acc[mi][ni][2], v3 = acc[mi][ni][3];
            if (mode == 0) {
                int hh = c >> 6, d = c & 63;
                *(__half2*)&g_Qh[(((size_t)bidx * HH + hh) * NN + n0r) * DHD + d] =
                    __floats2half2_rn(tanhf(v0) * 0.125f, tanhf(v1) * 0.125f);
                *(__half2*)&g_Qh[(((size_t)bidx * HH + hh) * NN + n0r + 8) * DHD + d] =
                    __floats2half2_rn(tanhf(v2) * 0.125f, tanhf(v3) * 0.125f);
            } else if (mode == 1) {
                if (c < INNERD) {
                    int hh = c >> 6, d = c & 63;
                    *(__half2*)&g_Kh[(((size_t)bidx * HH + hh) * MPAD + n0r + 1) * DHD + d] =
                        __floats2half2_rn(tanhf(v0), tanhf(v1));
                    *(__half2*)&g_Kh[(((size_t)bidx * HH + hh) * MPAD + n0r + 9) * DHD + d] =
                        __floats2half2_rn(tanhf(v2), tanhf(v3));
                } else {
                    int c2 = c - INNERD;
                    int hh = c2 >> 6, d = c2 & 63;
                    *(__half2*)&g_Vh[(((size_t)bidx * HH + hh) * MPAD + n0r + 1) * DHD + d] =
                        __floats2half2_rn(v0, v1);
                    *(__half2*)&g_Vh[(((size_t)bidx * HH + hh) * MPAD + n0r + 9) * DHD + d] =
                        __floats2half2_rn(v2, v3);
                }
            } else {
                float b0v = bias[c], b1v = bias[c + 1];
                *(float2*)&out[(size_t)r0 * 512 + c]       = make_float2(v0 + b0v, v1 + b1v);
                *(float2*)&out[(size_t)(r0 + 8) * 512 + c] = make_float2(v2 + b0v, v3 + b1v);
            }
        }
    }
}

// ---------------------------------------------------------------------------
__global__ void prep_bias_kernel(const unsigned int* __restrict__ cmask) {
    int t = blockIdx.x * 256 + threadIdx.x;
    if (t >= BB * MPAD) return;
    int b = t / MPAD, j = t % MPAD;
    float v, v2;
    if (j == 0)        { v = 0.f; v2 = 0.f; }
    else if (j <= MM)  { v = (cmask[b * MM + (j - 1)] != 0u) ? 0.f : -NEG_MAX; v2 = 0.f; }
    else               { v = -INFINITY; v2 = -INFINITY; }
    g_kbias[t] = v;
    g_kbias2[t] = v2;
}

__global__ void prep_kv_kernel(const float* __restrict__ null_key,
                               const float* __restrict__ null_value) {
    int bh = blockIdx.x;
    __half* Kb = g_Kh + (size_t)bh * MPAD * DHD;
    __half* Vb = g_Vh + (size_t)bh * MPAD * DHD;
    int t = threadIdx.x;
    if (t < DHD) {
        Kb[t] = __float2half_rn(tanhf(null_key[t]));
        Vb[t] = __float2half_rn(null_value[t]);
    }
    for (int idx = t; idx < DHD * (MPAD - MP); idx += 256) {
        int d = idx & 63, jr = idx >> 6;
        Kb[(size_t)(MP + jr) * DHD + d] = __float2half_rn(0.f);
        Vb[(size_t)(MP + jr) * DHD + d] = __float2half_rn(0.f);
    }
}

// ---------------------------------------------------------------------------
// Flash attention: fp16 mma, register P, K+V+bias all double-buffered,
// ONE __syncthreads per key tile.
// ---------------------------------------------------------------------------
struct __align__(16) AttnSmemH {
    __half Qs[128][72];       // [q][d]
    __half Kt[2][64][72];     // [j][d]
    __half Vs[2][64][72];     // [j][d]
    float kb[2][64];
    float kbq[2][64];
};

__device__ __forceinline__ void cp_kv_tile(AttnSmemH& s, int buf, const __half* Kb,
                                           const __half* Vb, int j0, int t) {
    #pragma unroll
    for (int i = 0; i < 2; i++) {
        int e = t + i * 256;
        int r = e >> 3, c8 = (e & 7) * 8;
        cpa16(&s.Kt[buf][r][c8], Kb + (size_t)(j0 + r) * DHD + c8);
        cpa16(&s.Vs[buf][r][c8], Vb + (size_t)(j0 + r) * DHD + c8);
    }
}

__global__ __launch_bounds__(256, 2) void attn_kernel(const unsigned int* __restrict__ qmask) {
    extern __shared__ char smem_raw[];
    AttnSmemH& s = *reinterpret_cast<AttnSmemH*>(smem_raw);

    int t = threadIdx.x, lane = t & 31, w = t >> 5;
    int n0 = blockIdx.x * QT;
    int h = blockIdx.y, b = blockIdx.z;
    int bh = b * HH + h;

    const __half* Qb = g_Qh + (size_t)bh * NN * DHD;
    const __half* Kb = g_Kh + (size_t)bh * MPAD * DHD;
    const __half* Vb = g_Vh + (size_t)bh * MPAD * DHD;
    const float* kb_base  = g_kbias  + b * MPAD;
    const float* kbq_base = g_kbias2 + b * MPAD;

    // Q tile + tile-0 K/V/bias
    #pragma unroll
    for (int i = 0; i < 4; i++) {
        int e = t + i * 256;
        int q = e >> 3, c8 = (e & 7) * 8;
        *(uint4*)&s.Qs[q][c8] = *(const uint4*)&Qb[(size_t)(n0 + q) * DHD + c8];
    }
    cp_kv_tile(s, 0, Kb, Vb, 0, t);
    CP_COMMIT();
    if (t < 64) {
        s.kb[0][t]  = kb_base[t];
        s.kbq[0][t] = kbq_base[t];
    }
    CP_WAIT(0);
    __syncthreads();

    int g = lane >> 2, cl = lane & 3;
    int row_lo = w * 16 + g;
    int a_lr = lane & 15, a_lc = (lane >> 4) * 8;

    uint32_t aq[4][4];
    #pragma unroll
    for (int ko = 0; ko < 4; ko++)
        ldsm4(aq[ko], smem_u32(&s.Qs[w * 16 + a_lr][ko * 16 + a_lc]));

    int qml = (qmask[b * NN + n0 + row_lo]     != 0u) ? 1 : 0;
    int qmh = (qmask[b * NN + n0 + row_lo + 8] != 0u) ? 1 : 0;

    float m_lo = -NEG_MAX, m_hi = -NEG_MAX, l_lo = 0.f, l_hi = 0.f;
    float oacc[8][4] = {};
    int p = 0;

    int k_lr = (lane & 7) + 8 * (lane >> 4);
    int k_lc = 8 * ((lane >> 3) & 1);
    int v_lr = (lane & 7) + 8 * ((lane >> 3) & 1);
    int v_lc = 8 * (lane >> 4);

    for (int kt = 0; kt < NTILES; kt++) {
        // prefetch next tile into buffer 1-p (no hazard: bottom barrier of
        // previous iteration separates these writes from prior reads)
        if (kt < NTILES - 1) {
            int j1 = (kt + 1) * KT;
            cp_kv_tile(s, 1 - p, Kb, Vb, j1, t);
            CP_COMMIT();
            if (t < 64) {
                s.kb[1 - p][t]  = kb_base[j1 + t];
                s.kbq[1 - p][t] = kbq_base[j1 + t];
            }
        }

        // ---- S = Q K^T from buffer p ----
        float sacc[8][4] = {};
        #pragma unroll
        for (int ko = 0; ko < 4; ko++) {
            #pragma unroll
            for (int ntp = 0; ntp < 4; ntp++) {
                uint32_t bf[4];
                ldsm4(bf, smem_u32(&s.Kt[p][ntp * 16 + k_lr][ko * 16 + k_lc]));
                mma16(sacc[ntp * 2],     aq[ko], bf[0], bf[1]);
                mma16(sacc[ntp * 2 + 1], aq[ko], bf[2], bf[3]);
            }
        }

        // ---- mask + online softmax ----
        float mx_lo = m_lo, mx_hi = m_hi;
        #pragma unroll
        for (int nt = 0; nt < 8; nt++) {
            int c = nt * 8 + 2 * cl;
            float kb0 = s.kb[p][c], kb1 = s.kb[p][c + 1];
            float kq0 = s.kbq[p][c], kq1 = s.kbq[p][c + 1];
            float x0 = qml ? sacc[nt][0] + kb0 : kq0;
            float x1 = qml ? sacc[nt][1] + kb1 : kq1;
            float x2 = qmh ? sacc[nt][2] + kb0 : kq0;
            float x3 = qmh ? sacc[nt][3] + kb1 : kq1;
            sacc[nt][0] = x0; sacc[nt][1] = x1; sacc[nt][2] = x2; sacc[nt][3] = x3;
            mx_lo = fmaxf(mx_lo, fmaxf(x0, x1));
            mx_hi = fmaxf(mx_hi, fmaxf(x2, x3));
        }
        mx_lo = fmaxf(mx_lo, __shfl_xor_sync(0xffffffffu, mx_lo, 1));
        mx_lo = fmaxf(mx_lo, __shfl_xor_sync(0xffffffffu, mx_lo, 2));
        mx_hi = fmaxf(mx_hi, __shfl_xor_sync(0xffffffffu, mx_hi, 1));
        mx_hi = fmaxf(mx_hi, __shfl_xor_sync(0xffffffffu, mx_hi, 2));

        float al_lo = __expf(m_lo - mx_lo); m_lo = mx_lo;
        float al_hi = __expf(m_hi - mx_hi); m_hi = mx_hi;

        uint32_t pf_lo[8], pf_hi[8];
        float sum_lo = 0.f, sum_hi = 0.f;
        #pragma unroll
        for (int nt = 0; nt < 8; nt++) {
            float p0 = __expf(sacc[nt][0] - mx_lo);
            float p1 = __expf(sacc[nt][1] - mx_lo);
            float p2 = __expf(sacc[nt][2] - mx_hi);
            float p3 = __expf(sacc[nt][3] - mx_hi);
            __half2 hlo = __floats2half2_rn(p0, p1);
            __half2 hhi = __floats2half2_rn(p2, p3);
            float2 flo = __half22float2(hlo), fhi = __half22float2(hhi);
            sum_lo += flo.x + flo.y;
            sum_hi += fhi.x + fhi.y;
            pf_lo[nt] = *(uint32_t*)&hlo;
            pf_hi[nt] = *(uint32_t*)&hhi;
        }
        sum_lo += __shfl_xor_sync(0xffffffffu, sum_lo, 1);
        sum_lo += __shfl_xor_sync(0xffffffffu, sum_lo, 2);
        sum_hi += __shfl_xor_sync(0xffffffffu, sum_hi, 1);
        sum_hi += __shfl_xor_sync(0xffffffffu, sum_hi, 2);
        l_lo = l_lo * al_lo + sum_lo;
        l_hi = l_hi * al_hi + sum_hi;

        // ---- rescale + O += P V from buffer p ----
        #pragma unroll
        for (int nt = 0; nt < 8; nt++) {
            oacc[nt][0] *= al_lo; oacc[nt][1] *= al_lo;
            oacc[nt][2] *= al_hi; oacc[nt][3] *= al_hi;
        }
        #pragma unroll
        for (int ko2 = 0; ko2 < 4; ko2++) {
            uint32_t pa[4] = { pf_lo[ko2 * 2], pf_hi[ko2 * 2],
                               pf_lo[ko2 * 2 + 1], pf_hi[ko2 * 2 + 1] };
            #pragma unroll
            for (int ntp = 0; ntp < 4; ntp++) {
                uint32_t bf[4];
                ldsm4t(bf, smem_u32(&s.Vs[p][ko2 * 16 + v_lr][ntp * 16 + v_lc]));
                mma16(oacc[ntp * 2],     pa, bf[0], bf[1]);
                mma16(oacc[ntp * 2 + 1], pa, bf[2], bf[3]);
            }
        }

        if (kt < NTILES - 1) {
            CP_WAIT(0);
            __syncthreads();
        }
        p ^= 1;
    }

    float li_lo = 1.f / l_lo, li_hi = 1.f / l_hi;
    #pragma unroll
    for (int nt = 0; nt < 8; nt++) {
        int c = nt * 8 + 2 * cl;
        size_t base_lo = ((size_t)b * NN + n0 + row_lo) * INNERD + h * DHD + c;
        size_t base_hi = ((size_t)b * NN + n0 + row_lo + 8) * INNERD + h * DHD + c;
        *(__half2*)&g_Oh[base_lo] = __floats2half2_rn(oacc[nt][0] * li_lo, oacc[nt][1] * li_lo);
        *(__half2*)&g_Oh[base_hi] = __floats2half2_rn(oacc[nt][2] * li_hi, oacc[nt][3] * li_hi);
    }
}

// ---------------------------------------------------------------------------
extern "C" void kernel_launch(void* const* d_in, const int* in_sizes, int n_in,
                              void* d_out, int out_size) {
    const float* x            = (const float*)d_in[0];
    const float* ctx          = (const float*)d_in[1];
    const unsigned int* mask  = (const unsigned int*)d_in[2];
    const unsigned int* cmask = (const unsigned int*)d_in[3];
    const float* Wq  = (const float*)d_in[4];
    const float* Wkv = (const float*)d_in[5];
    const float* Wo  = (const float*)d_in[6];
    const float* bo  = (const float*)d_in[7];
    const float* nk  = (const float*)d_in[8];
    const float* nv  = (const float*)d_in[9];
    float* out = (float*)d_out;

    static int inited = 0;
    if (!inited) {
        cudaFuncSetAttribute(attn_kernel, cudaFuncAttributeMaxDynamicSharedMemorySize,
                             (int)sizeof(AttnSmemH));
        inited = 1;
    }

    __half *oh;
    cudaGetSymbolAddress((void**)&oh, g_Oh);

    round_all_kernel<<<(N4_TOT + 255) / 256, 256>>>(x, ctx, Wq, Wkv, Wo);
    prep_bias_kernel<<<(BB * MPAD + 255) / 256, 256>>>(cmask);
    prep_kv_kernel<<<BB * HH, 256>>>(nk, nv);

    // fused Q + KV projection (mode 3 dispatch)
    dim3 gqkv(12, 64);
    gemm_mma_h<<<gqkv, 256>>>(nullptr, nullptr, nullptr, nullptr, 0, 3);

    dim3 ga(NN / QT, HH, BB);                        // (16, 8, 4)
    attn_kernel<<<ga, 256, sizeof(AttnSmemH)>>>(mask);

    __half *woh;
    cudaGetSymbolAddress((void**)&woh, g_woh);
    dim3 g2(512 / 128, (BB * NN) / 128);             // (4, 64)
    gemm_mma_h<<<g2, 256>>>(oh, woh, bo, out, 512, 2);
}